// round 14
// baseline (speedup 1.0000x reference)
#include <cuda_runtime.h>
#include <cuda_bf16.h>
#include <math.h>

#define BB 32
#define TT 64
#define BT 2048
#define HID 200
#define FEAT 6144
#define SPLITS 8

// -------------------- scratch (device globals; no allocs) --------------------
__device__ float g_xt  [BT * 3  * 1024];
__device__ float g_e1  [BT * 8  * 1024];
__device__ float g_e2  [BT * 16 * 256];
__device__ float g_e3  [BT * 32 * 64];
__device__ float g_d2  [BT * 16 * 256];
__device__ float g_feat[BT * FEAT];
__device__ float g_h2  [BT * HID];
__device__ float g_part[SPLITS * BT * HID];

// -------------------- permute [B,C,H,W,T] -> [B*T,C,H,W] --------------------
__global__ void permute_kernel(const float* __restrict__ x, float* __restrict__ xt) {
    int bidx = blockIdx.x;
    int h = bidx & 31;
    int c = (bidx >> 5) % 3;
    int b = bidx / 96;
    __shared__ float s[32][65];
    const float* src = x + (size_t)(((b * 3 + c) * 32 + h) * 32) * 64;
    for (int i = threadIdx.x; i < 2048; i += blockDim.x) {
        int w = i >> 6, t = i & 63;
        s[w][t] = src[i];
    }
    __syncthreads();
    for (int i = threadIdx.x; i < 2048; i += blockDim.x) {
        int t = i >> 5, w = i & 31;
        xt[((size_t)((b * 64 + t) * 3 + c) << 10) + (h << 5) + w] = s[w][t];
    }
}

// -------------------- standard conv3x3 (+optional 2x2 maxpool of input, +ReLU)
template<int CA, int COUT, int COUT_T, int HS, int NBT, int NPIX, bool POOL>
__global__ void __launch_bounds__(256, 2)
conv_std_k(const float* __restrict__ inA, const float* __restrict__ wgt,
           const float* __restrict__ bias, float* __restrict__ out)
{
    constexpr int GP   = COUT / COUT_T;
    constexpr int PXT  = HS * HS / NPIX;
    constexpr int HP   = HS + 1;
    constexpr int CSZ  = HS * HP;
    constexpr int ASZP = CA * CSZ;
    constexpr int WSZ  = COUT * CA * 9;
    extern __shared__ float sm[];
    float* sW  = sm;
    float* sBi = sW + WSZ;
    float* sIn = sBi + COUT;

    const int tid = threadIdx.x, NT = blockDim.x;
    const int bt0 = blockIdx.x * NBT;

    for (int i = tid; i < WSZ; i += NT) {
        int co = i % COUT;
        int rest = i / COUT;
        int ci = rest / 9, kk = rest % 9;
        sW[i] = wgt[(co * CA + ci) * 9 + kk];
    }
    for (int i = tid; i < COUT; i += NT) sBi[i] = bias[i];

    if (POOL) {
        for (int i = tid; i < NBT * CA * HS * HS / 2; i += NT) {
            int e2 = i * 2;
            int nn = e2 / (CA * HS * HS), rr = e2 % (CA * HS * HS);
            int c = rr / (HS * HS), pp = rr % (HS * HS);
            int hh = pp / HS, ww = pp % HS;
            const float* s = inA + (size_t)((bt0 + nn) * CA + c) * (4 * HS * HS)
                                 + (2 * hh) * (2 * HS) + 2 * ww;
            float4 r0 = *reinterpret_cast<const float4*>(s);
            float4 r1 = *reinterpret_cast<const float4*>(s + 2 * HS);
            float* d = sIn + nn * ASZP + c * CSZ + hh * HP + ww;
            d[0] = fmaxf(fmaxf(r0.x, r0.y), fmaxf(r1.x, r1.y));
            d[1] = fmaxf(fmaxf(r0.z, r0.w), fmaxf(r1.z, r1.w));
        }
    } else {
        for (int i = tid; i < NBT * CA * HS * HS / 4; i += NT) {
            int e4 = i * 4;
            int nn = e4 / (CA * HS * HS), rr = e4 % (CA * HS * HS);
            int c = rr / (HS * HS), pp = rr % (HS * HS);
            int hh = pp / HS, ww = pp % HS;
            float4 v = *reinterpret_cast<const float4*>(
                inA + (size_t)(bt0 + nn) * (CA * HS * HS) + rr);
            float* d = sIn + nn * ASZP + c * CSZ + hh * HP + ww;
            d[0] = v.x; d[1] = v.y; d[2] = v.z; d[3] = v.w;
        }
    }
    __syncthreads();

    const int n   = tid / (GP * PXT);
    const int r   = tid % (GP * PXT);
    const int cog = r / PXT;
    const int p   = r % PXT;
    const int h   = p / (HS / NPIX);
    const int w0  = (p % (HS / NPIX)) * NPIX;
    const float* sI = sIn + n * ASZP;

    float acc[COUT_T][NPIX];
    #pragma unroll
    for (int co = 0; co < COUT_T; co++) {
        float b = sBi[cog * COUT_T + co];
        #pragma unroll
        for (int j = 0; j < NPIX; j++) acc[co][j] = b;
    }

    #pragma unroll 1
    for (int ci = 0; ci < CA; ci++) {
        const float* ch = sI + ci * CSZ;
        #pragma unroll
        for (int kh = 0; kh < 3; kh++) {
            int ih = h + kh - 1;
            bool rowok = (ih >= 0) && (ih < HS);
            float v[NPIX + 2];
            #pragma unroll
            for (int j = 0; j < NPIX + 2; j++) {
                int iw = w0 + j - 1;
                v[j] = (rowok && iw >= 0 && iw < HS) ? ch[ih * HP + iw] : 0.f;
            }
            const float* wr = sW + (ci * 9 + kh * 3) * COUT + cog * COUT_T;
            #pragma unroll
            for (int co = 0; co < COUT_T; co++) {
                float wa = wr[co], wb = wr[COUT + co], wc = wr[2 * COUT + co];
                #pragma unroll
                for (int j = 0; j < NPIX; j++)
                    acc[co][j] = fmaf(wa, v[j], fmaf(wb, v[j + 1], fmaf(wc, v[j + 2], acc[co][j])));
            }
        }
    }

    const int btn = bt0 + n;
    #pragma unroll
    for (int co = 0; co < COUT_T; co++) {
        float* op = out + (size_t)((btn * COUT + cog * COUT_T + co) * HS + h) * HS + w0;
        #pragma unroll
        for (int j = 0; j < NPIX; j += 4)
            *reinterpret_cast<float4*>(op + j) =
                make_float4(fmaxf(acc[co][j], 0.f), fmaxf(acc[co][j + 1], 0.f),
                            fmaxf(acc[co][j + 2], 0.f), fmaxf(acc[co][j + 3], 0.f));
    }
}

// -------------------- decoder conv3x3 over [up2x(A), B] (+opt fused mask) ----
// A-part weights parity-folded ONCE into SMEM (both h-parities); B raw weights.
template<int CA, int CB, int COUT, int COUT_T, int HS, int NBT, int NPIX, bool FUSE>
__global__ void __launch_bounds__(256, 2)
conv_up_k(const float* __restrict__ inA, const float* __restrict__ inB,
          const float* __restrict__ wgt, const float* __restrict__ bias,
          const float* __restrict__ xtp, const float* __restrict__ owp,
          const float* __restrict__ obp, float* __restrict__ out)
{
    constexpr int CIN  = CA + CB;
    constexpr int HA   = HS / 2;
    constexpr int HAP  = HA + 1;
    constexpr int HP   = HS + 1;
    constexpr int CASZ = HA * HAP;
    constexpr int CBSZ = HS * HP;
    constexpr int ASZP = CA * CASZ;
    constexpr int TSZ  = ASZP + CB * CBSZ;
    constexpr int GP   = COUT / COUT_T;
    constexpr int PXT  = HS * HS / NPIX;
    constexpr int WBSZ = CB * 9 * COUT;          // raw B weights (transposed)
    constexpr int WFSZ = 2 * CA * 8 * COUT;      // folded A weights, both parities
    constexpr int NC   = NPIX / 2 + 2;

    extern __shared__ float sm[];
    float* sWB = sm;                  // [CB*9][COUT]
    float* sWF = sWB + WBSZ;          // [par][ci][8][COUT]
    float* sBi = sWF + WFSZ;
    float* sOW = sBi + COUT;
    float* sIn = sOW + 18;

    const int tid = threadIdx.x, NT = blockDim.x;
    const int bt0 = blockIdx.x * NBT;

    for (int i = tid; i < WBSZ; i += NT) {
        int co = i % COUT;
        int rest = i / COUT;
        int ci = rest / 9, kk = rest % 9;
        sWB[i] = wgt[(co * CIN + CA + ci) * 9 + kk];
    }
    // folded A weights: t in {sA0,sA01,sA12,sA2,sB0,sB01,sB12,sB2}
    for (int i = tid; i < WFSZ; i += NT) {
        int co  = i % COUT;
        int t   = (i / COUT) % 8;
        int ci  = (i / (COUT * 8)) % CA;
        int par = i / (COUT * 8 * CA);          // 0 = h even, 1 = h odd
        const float* wp = wgt + (co * CIN + ci) * 9;
        float w00 = wp[0], w01 = wp[1], w02 = wp[2];
        float w10 = wp[3], w11 = wp[4], w12 = wp[5];
        float w20 = wp[6], w21 = wp[7], w22 = wp[8];
        float rA0 = par ? (w00 + w10) : w00;
        float rA1 = par ? (w01 + w11) : w01;
        float rA2 = par ? (w02 + w12) : w02;
        float rB0 = par ? w20 : (w10 + w20);
        float rB1 = par ? w21 : (w11 + w21);
        float rB2 = par ? w22 : (w12 + w22);
        float v;
        switch (t) {
            case 0: v = rA0;        break;
            case 1: v = rA0 + rA1;  break;
            case 2: v = rA1 + rA2;  break;
            case 3: v = rA2;        break;
            case 4: v = rB0;        break;
            case 5: v = rB0 + rB1;  break;
            case 6: v = rB1 + rB2;  break;
            default: v = rB2;       break;
        }
        sWF[i] = v;
    }
    for (int i = tid; i < COUT; i += NT) sBi[i] = bias[i];
    if (FUSE) {
        for (int i = tid; i < 18; i += NT) sOW[i] = (i < 16) ? owp[i] : obp[i - 16];
    }
    for (int i = tid; i < NBT * CA * HA * HA / 4; i += NT) {
        int e4 = i * 4;
        int nn = e4 / (CA * HA * HA), rr = e4 % (CA * HA * HA);
        int c = rr / (HA * HA), pp = rr % (HA * HA);
        float4 v = *reinterpret_cast<const float4*>(
            inA + (size_t)(bt0 + nn) * (CA * HA * HA) + rr);
        float* d = sIn + nn * TSZ + c * CASZ + (pp / HA) * HAP + (pp % HA);
        d[0] = v.x; d[1] = v.y; d[2] = v.z; d[3] = v.w;
    }
    for (int i = tid; i < NBT * CB * HS * HS / 4; i += NT) {
        int e4 = i * 4;
        int nn = e4 / (CB * HS * HS), rr = e4 % (CB * HS * HS);
        int c = rr / (HS * HS), pp = rr % (HS * HS);
        float4 v = *reinterpret_cast<const float4*>(
            inB + (size_t)(bt0 + nn) * (CB * HS * HS) + rr);
        float* d = sIn + nn * TSZ + ASZP + c * CBSZ + (pp / HS) * HP + (pp % HS);
        d[0] = v.x; d[1] = v.y; d[2] = v.z; d[3] = v.w;
    }
    __syncthreads();

    const int n   = tid / (GP * PXT);
    const int r   = tid % (GP * PXT);
    const int cog = r / PXT;
    const int p   = r % PXT;
    const int h   = p / (HS / NPIX);
    const int w0  = (p % (HS / NPIX)) * NPIX;
    const float* sI = sIn + n * TSZ;

    float acc[COUT_T][NPIX];
    #pragma unroll
    for (int co = 0; co < COUT_T; co++) {
        float b = sBi[cog * COUT_T + co];
        #pragma unroll
        for (int j = 0; j < NPIX; j++) acc[co][j] = b;
    }

    // ---- A part: coarse 2x2 stencil with precomputed folded weights ----
    const int  a    = h >> 1;
    const bool hodd = (h & 1) != 0;
    const int  rowA = hodd ? a : a - 1;
    const int  rowB = hodd ? a + 1 : a;
    const int  cs0  = (w0 >> 1) - 1;
    const float* sWFp = sWF + (hodd ? CA * 8 * COUT : 0);

    #pragma unroll 1
    for (int ci = 0; ci < CA; ci++) {
        const float* ch = sI + ci * CASZ;
        float cAr[NC], cBr[NC];
        #pragma unroll
        for (int k = 0; k < NC; k++) {
            int cc = cs0 + k;
            bool cok = (cc >= 0) && (cc < HA);
            cAr[k] = (cok && rowA >= 0) ? ch[rowA * HAP + cc] : 0.f;
            cBr[k] = (cok && rowB < HA) ? ch[rowB * HAP + cc] : 0.f;
        }
        const float* wf = sWFp + ci * 8 * COUT + cog * COUT_T;
        #pragma unroll
        for (int co = 0; co < COUT_T; co++) {
            float sA0  = wf[0 * COUT + co];
            float sA01 = wf[1 * COUT + co];
            float sA12 = wf[2 * COUT + co];
            float sA2  = wf[3 * COUT + co];
            float sB0  = wf[4 * COUT + co];
            float sB01 = wf[5 * COUT + co];
            float sB12 = wf[6 * COUT + co];
            float sB2  = wf[7 * COUT + co];
            #pragma unroll
            for (int j = 0; j < NPIX; j++) {
                int lb = (j >> 1) + 1;
                if ((j & 1) == 0) {
                    acc[co][j] = fmaf(cAr[lb - 1], sA0,  acc[co][j]);
                    acc[co][j] = fmaf(cAr[lb],     sA12, acc[co][j]);
                    acc[co][j] = fmaf(cBr[lb - 1], sB0,  acc[co][j]);
                    acc[co][j] = fmaf(cBr[lb],     sB12, acc[co][j]);
                } else {
                    acc[co][j] = fmaf(cAr[lb],     sA01, acc[co][j]);
                    acc[co][j] = fmaf(cAr[lb + 1], sA2,  acc[co][j]);
                    acc[co][j] = fmaf(cBr[lb],     sB01, acc[co][j]);
                    acc[co][j] = fmaf(cBr[lb + 1], sB2,  acc[co][j]);
                }
            }
        }
    }

    // ---- B part: fine 3x3, raw transposed weights ----
    #pragma unroll 1
    for (int ci = 0; ci < CB; ci++) {
        const float* ch = sI + ASZP + ci * CBSZ;
        #pragma unroll
        for (int kh = 0; kh < 3; kh++) {
            int ih = h + kh - 1;
            bool rowok = (ih >= 0) && (ih < HS);
            float v[NPIX + 2];
            #pragma unroll
            for (int j = 0; j < NPIX + 2; j++) {
                int iw = w0 + j - 1;
                v[j] = (rowok && iw >= 0 && iw < HS) ? ch[ih * HP + iw] : 0.f;
            }
            const float* wr = sWB + (ci * 9 + kh * 3) * COUT + cog * COUT_T;
            #pragma unroll
            for (int co = 0; co < COUT_T; co++) {
                float wa = wr[co], wb = wr[COUT + co], wc = wr[2 * COUT + co];
                #pragma unroll
                for (int j = 0; j < NPIX; j++)
                    acc[co][j] = fmaf(wa, v[j], fmaf(wb, v[j + 1], fmaf(wc, v[j + 2], acc[co][j])));
            }
        }
    }

    const int btn = bt0 + n;
    if constexpr (FUSE) {
        float m0a[NPIX], m1a[NPIX];
        #pragma unroll
        for (int j = 0; j < NPIX; j++) {
            float l0 = sOW[16], l1 = sOW[17];
            #pragma unroll
            for (int co = 0; co < COUT_T; co++) {
                float dv = fmaxf(acc[co][j], 0.f);
                l0 = fmaf(dv, sOW[co], l0);
                l1 = fmaf(dv, sOW[8 + co], l1);
            }
            float mx = fmaxf(fmaxf(l0, l1), 1.0f);
            float e0 = expf(l0 - mx), e1v = expf(l1 - mx), e2v = expf(1.0f - mx);
            float inv = 1.0f / (e0 + e1v + e2v);
            m0a[j] = e0 * inv;
            m1a[j] = e1v * inv;
        }
        const float* xp = xtp + ((size_t)btn * 3 << 10) + (h << 5) + w0;
        float* fp = out + (size_t)btn * FEAT + (h << 5) + w0;
        #pragma unroll
        for (int c = 0; c < 3; c++) {
            float4 xa = *reinterpret_cast<const float4*>(xp + ((size_t)c << 10));
            float4 xb = *reinterpret_cast<const float4*>(xp + ((size_t)c << 10) + 4);
            float* f0 = fp + ((size_t)c << 10);
            float* f1 = fp + ((size_t)(3 + c) << 10);
            *reinterpret_cast<float4*>(f0) =
                make_float4(m0a[0] * xa.x, m0a[1] * xa.y, m0a[2] * xa.z, m0a[3] * xa.w);
            *reinterpret_cast<float4*>(f0 + 4) =
                make_float4(m0a[4] * xb.x, m0a[5] * xb.y, m0a[6] * xb.z, m0a[7] * xb.w);
            *reinterpret_cast<float4*>(f1) =
                make_float4(m1a[0] * xa.x, m1a[1] * xa.y, m1a[2] * xa.z, m1a[3] * xa.w);
            *reinterpret_cast<float4*>(f1 + 4) =
                make_float4(m1a[4] * xb.x, m1a[5] * xb.y, m1a[6] * xb.z, m1a[7] * xb.w);
        }
    } else {
        #pragma unroll
        for (int co = 0; co < COUT_T; co++) {
            float* op = out + (size_t)((btn * COUT + cog * COUT_T + co) * HS + h) * HS + w0;
            #pragma unroll
            for (int j = 0; j < NPIX; j += 4)
                *reinterpret_cast<float4*>(op + j) =
                    make_float4(fmaxf(acc[co][j], 0.f), fmaxf(acc[co][j + 1], 0.f),
                                fmaxf(acc[co][j + 2], 0.f), fmaxf(acc[co][j + 3], 0.f));
        }
    }
}

// -------------------- GEMM1: split-K, tf32 mma.sync, BK32 double-buffered ----
__device__ __forceinline__ unsigned f2tf(float f) {
    unsigned r;
    asm("cvt.rna.tf32.f32 %0, %1;" : "=r"(r) : "f"(f));
    return r;
}

__global__ void __launch_bounds__(256)
sgemm1_k(const float* __restrict__ A, const float* __restrict__ Bm,
         float* __restrict__ Cpart)
{
    constexpr int M = BT, N = HID, K = FEAT;
    constexpr int BM = 128, BN = 64, BK = 32;
    constexpr int KS = K / SPLITS;                 // 768
    constexpr int NTILE = KS / BK;                 // 24
    constexpr int SAP = BM + 8;                    // 136
    constexpr int SBP = BN + 8;                    // 72

    __shared__ float sA[2][BK][SAP];
    __shared__ float sB[2][BK][SBP];

    const int tid  = threadIdx.x;
    const int warp = tid >> 5;
    const int lane = tid & 31;
    const int gid  = lane >> 2;
    const int tig  = lane & 3;
    const int wm   = warp & 3;
    const int wn   = warp >> 2;
    const int m_w  = wm * 32;
    const int n_w  = wn * 32;

    const int bm = blockIdx.y * BM;
    const int bn = blockIdx.x * BN;
    const int kbase = blockIdx.z * KS;

    const int c8 = tid & 7;                        // k-quad 0..7 (8*4 = 32)
    const int r0 = tid >> 3;                       // row 0..31
    const int bkk = tid >> 4;                      // B row 0..15 (and +16)
    const int bcc = (tid & 15) * 4;

    float c[2][4][4];
    #pragma unroll
    for (int mi = 0; mi < 2; mi++)
        #pragma unroll
        for (int ni = 0; ni < 4; ni++)
            #pragma unroll
            for (int f = 0; f < 4; f++) c[mi][ni][f] = 0.f;

    // fill helper (expanded inline twice)
    #define FILL_TILE(BUF, KOFF)                                                        \
    {                                                                                    \
        int k0f = (KOFF);                                                                \
        _Pragma("unroll")                                                                \
        for (int q = 0; q < 4; q++) {                                                    \
            int rr = r0 + 32 * q;                                                        \
            float4 av = *reinterpret_cast<const float4*>(                                \
                &A[(size_t)(bm + rr) * K + k0f + c8 * 4]);                               \
            sA[BUF][c8 * 4 + 0][rr] = __uint_as_float(f2tf(av.x));                       \
            sA[BUF][c8 * 4 + 1][rr] = __uint_as_float(f2tf(av.y));                       \
            sA[BUF][c8 * 4 + 2][rr] = __uint_as_float(f2tf(av.z));                       \
            sA[BUF][c8 * 4 + 3][rr] = __uint_as_float(f2tf(av.w));                       \
        }                                                                                \
        _Pragma("unroll")                                                                \
        for (int q = 0; q < 2; q++) {                                                    \
            int kk = bkk + 16 * q;                                                       \
            int gcol = bn + bcc;                                                         \
            float b0 = (gcol + 0 < N) ? Bm[(size_t)(k0f + kk) * N + gcol + 0] : 0.f;     \
            float b1 = (gcol + 1 < N) ? Bm[(size_t)(k0f + kk) * N + gcol + 1] : 0.f;     \
            float b2 = (gcol + 2 < N) ? Bm[(size_t)(k0f + kk) * N + gcol + 2] : 0.f;     \
            float b3 = (gcol + 3 < N) ? Bm[(size_t)(k0f + kk) * N + gcol + 3] : 0.f;     \
            sB[BUF][kk][bcc + 0] = __uint_as_float(f2tf(b0));                            \
            sB[BUF][kk][bcc + 1] = __uint_as_float(f2tf(b1));                            \
            sB[BUF][kk][bcc + 2] = __uint_as_float(f2tf(b2));                            \
            sB[BUF][kk][bcc + 3] = __uint_as_float(f2tf(b3));                            \
        }                                                                                \
    }

    FILL_TILE(0, kbase)
    __syncthreads();

    #pragma unroll 1
    for (int t = 0; t < NTILE; t++) {
        int cur = t & 1;
        if (t + 1 < NTILE) FILL_TILE(!cur ? 1 : 0, kbase + (t + 1) * BK)

        #pragma unroll
        for (int kc = 0; kc < BK; kc += 8) {
            unsigned bf[4][2];
            #pragma unroll
            for (int ni = 0; ni < 4; ni++) {
                bf[ni][0] = __float_as_uint(sB[cur][kc + tig][n_w + ni * 8 + gid]);
                bf[ni][1] = __float_as_uint(sB[cur][kc + tig + 4][n_w + ni * 8 + gid]);
            }
            #pragma unroll
            for (int mi = 0; mi < 2; mi++) {
                int mrow = m_w + mi * 16 + gid;
                unsigned a0 = __float_as_uint(sA[cur][kc + tig][mrow]);
                unsigned a1 = __float_as_uint(sA[cur][kc + tig][mrow + 8]);
                unsigned a2 = __float_as_uint(sA[cur][kc + tig + 4][mrow]);
                unsigned a3 = __float_as_uint(sA[cur][kc + tig + 4][mrow + 8]);
                #pragma unroll
                for (int ni = 0; ni < 4; ni++) {
                    asm volatile(
                        "mma.sync.aligned.m16n8k8.row.col.f32.tf32.tf32.f32 "
                        "{%0,%1,%2,%3}, {%4,%5,%6,%7}, {%8,%9}, {%0,%1,%2,%3};"
                        : "+f"(c[mi][ni][0]), "+f"(c[mi][ni][1]),
                          "+f"(c[mi][ni][2]), "+f"(c[mi][ni][3])
                        : "r"(a0), "r"(a1), "r"(a2), "r"(a3),
                          "r"(bf[ni][0]), "r"(bf[ni][1]));
                }
            }
        }
        __syncthreads();
    }
    #undef FILL_TILE

    float* Cp = Cpart + (size_t)blockIdx.z * M * N;
    #pragma unroll
    for (int mi = 0; mi < 2; mi++) {
        int row0 = bm + m_w + mi * 16 + gid;
        #pragma unroll
        for (int ni = 0; ni < 4; ni++) {
            int col0 = bn + n_w + ni * 8 + 2 * tig;
            if (col0 < N) {
                Cp[(size_t)row0 * N + col0]       = c[mi][ni][0];
                Cp[(size_t)(row0 + 8) * N + col0] = c[mi][ni][2];
            }
            if (col0 + 1 < N) {
                Cp[(size_t)row0 * N + col0 + 1]       = c[mi][ni][1];
                Cp[(size_t)(row0 + 8) * N + col0 + 1] = c[mi][ni][3];
            }
        }
    }
}

// -------------------- GEMM2 with fused split-K reduce of h1 ------------------
__global__ void __launch_bounds__(256)
sgemm2_k(const float* __restrict__ part, const float* __restrict__ ab,
         const float* __restrict__ Bm, const float* __restrict__ bias,
         float* __restrict__ C)
{
    constexpr int M = BT, N = HID, K = HID;
    constexpr int BM = 64, BN = 64, BK = 16;
    __shared__ float sA[BK][BM + 1];
    __shared__ float sB[BK][BN];
    const int tid = threadIdx.x;
    const int tx = tid % 16;
    const int ty = tid / 16;
    const int bm = blockIdx.y * BM;
    const int bn = blockIdx.x * BN;

    float acc[4][4];
    #pragma unroll
    for (int i = 0; i < 4; i++)
        #pragma unroll
        for (int j = 0; j < 4; j++) acc[i][j] = 0.f;

    for (int k0 = 0; k0 < K; k0 += BK) {
        for (int i = tid; i < BM * BK; i += 256) {
            int m = i / BK, kk = i % BK;
            float v = 0.f;
            if (k0 + kk < K) {
                size_t off = (size_t)(bm + m) * K + k0 + kk;
                float t = ab[k0 + kk];
                #pragma unroll
                for (int s = 0; s < SPLITS; s++) t += part[(size_t)s * M * K + off];
                v = fmaxf(t, 0.f);
            }
            sA[kk][m] = v;
        }
        for (int i = tid; i < BK * BN; i += 256) {
            int kk = i / BN, n = i % BN;
            sB[kk][n] = (k0 + kk < K && bn + n < N) ? Bm[(size_t)(k0 + kk) * N + bn + n] : 0.f;
        }
        __syncthreads();
        #pragma unroll
        for (int kk = 0; kk < BK; kk++) {
            float a[4], b[4];
            #pragma unroll
            for (int i = 0; i < 4; i++) a[i] = sA[kk][ty * 4 + i];
            #pragma unroll
            for (int j = 0; j < 4; j++) b[j] = sB[kk][tx * 4 + j];
            #pragma unroll
            for (int i = 0; i < 4; i++)
                #pragma unroll
                for (int j = 0; j < 4; j++) acc[i][j] = fmaf(a[i], b[j], acc[i][j]);
        }
        __syncthreads();
    }

    #pragma unroll
    for (int i = 0; i < 4; i++) {
        int m = bm + ty * 4 + i;
        #pragma unroll
        for (int j = 0; j < 4; j++) {
            int n = bn + tx * 4 + j;
            if (n >= N) continue;
            C[(size_t)m * N + n] = fmaxf(acc[i][j] + bias[n], 0.f);
        }
    }
}

// -------------------- final 200->4 + tanh scale ------------------------------
__global__ void loc3_kernel(const float* __restrict__ h2, const float* __restrict__ w3,
                            const float* __restrict__ b3, float* __restrict__ out)
{
    int idx = blockIdx.x * blockDim.x + threadIdx.x;
    if (idx >= BT * 4) return;
    int m = idx >> 2, j = idx & 3;
    float acc = b3[j];
    const float* hp = h2 + (size_t)m * HID;
    #pragma unroll 8
    for (int k = 0; k < HID; k++) acc = fmaf(hp[k], w3[k * 4 + j], acc);
    out[idx] = tanhf(acc) * 16.f + 16.f;
}

// -------------------- launch --------------------------------------------------
extern "C" void kernel_launch(void* const* d_in, const int* in_sizes, int n_in,
                              void* d_out, int out_size)
{
    const float* x   = (const float*)d_in[0];
    const float* ew1 = (const float*)d_in[1];
    const float* eb1 = (const float*)d_in[2];
    const float* ew2 = (const float*)d_in[3];
    const float* eb2 = (const float*)d_in[4];
    const float* ew3 = (const float*)d_in[5];
    const float* eb3 = (const float*)d_in[6];
    const float* dw2 = (const float*)d_in[7];
    const float* db2 = (const float*)d_in[8];
    const float* dw1 = (const float*)d_in[9];
    const float* db1 = (const float*)d_in[10];
    const float* ow  = (const float*)d_in[11];
    const float* ob  = (const float*)d_in[12];
    const float* lw1 = (const float*)d_in[13];
    const float* lb1 = (const float*)d_in[14];
    const float* lw2 = (const float*)d_in[15];
    const float* lb2 = (const float*)d_in[16];
    const float* lw3 = (const float*)d_in[17];
    const float* lb3 = (const float*)d_in[18];
    float* out = (float*)d_out;

    float *xt, *e1, *e2, *e3, *d2v, *feat, *h2, *part;
    cudaGetSymbolAddress((void**)&xt,   g_xt);
    cudaGetSymbolAddress((void**)&e1,   g_e1);
    cudaGetSymbolAddress((void**)&e2,   g_e2);
    cudaGetSymbolAddress((void**)&e3,   g_e3);
    cudaGetSymbolAddress((void**)&d2v,  g_d2);
    cudaGetSymbolAddress((void**)&feat, g_feat);
    cudaGetSymbolAddress((void**)&h2,   g_h2);
    cudaGetSymbolAddress((void**)&part, g_part);

    constexpr int SM_E1 = (3 * 8 * 9  + 8  + 2 * 3 * 32 * 33) * 4;
    constexpr int SM_E2 = (8 * 16 * 9 + 16 + 4 * 8 * 16 * 17) * 4;
    constexpr int SM_E3 = (16 * 32 * 9 + 32 + 8 * 16 * 8 * 9) * 4;
    // conv_up: WB raw B wgts + WF folded A wgts + bias + 18 + input
    constexpr int SM_D2 = (16 * 9 * 16 + 2 * 32 * 8 * 16 + 16 + 18
                           + 2 * (32 * 8 * 9 + 16 * 16 * 17)) * 4;     // 95368
    constexpr int SM_D1 = (8 * 9 * 8 + 2 * 16 * 8 * 8 + 8 + 18
                           + 2 * (16 * 16 * 17 + 8 * 32 * 33)) * 4;    // 113000

    cudaFuncSetAttribute((const void*)conv_std_k<8, 16, 8, 16, 4, 8, true>,
                         cudaFuncAttributeMaxDynamicSharedMemorySize, SM_E2);
    cudaFuncSetAttribute((const void*)conv_std_k<16, 32, 8, 8, 8, 8, true>,
                         cudaFuncAttributeMaxDynamicSharedMemorySize, SM_E3);
    cudaFuncSetAttribute((const void*)conv_up_k<32, 16, 16, 4, 16, 2, 8, false>,
                         cudaFuncAttributeMaxDynamicSharedMemorySize, SM_D2);
    cudaFuncSetAttribute((const void*)conv_up_k<16, 8, 8, 8, 32, 2, 8, true>,
                         cudaFuncAttributeMaxDynamicSharedMemorySize, SM_D1);

    // 1) permute
    permute_kernel<<<32 * 3 * 32, 256>>>(x, xt);
    // 2) e1 = relu(conv 3->8 @32)
    conv_std_k<3, 8, 8, 32, 2, 8, false><<<BT / 2, 256, SM_E1>>>(xt, ew1, eb1, e1);
    // 3) e2 = relu(conv pool(e1) 8->16 @16)
    conv_std_k<8, 16, 8, 16, 4, 8, true><<<BT / 4, 256, SM_E2>>>(e1, ew2, eb2, e2);
    // 4) e3 = relu(conv pool(e2) 16->32 @8)
    conv_std_k<16, 32, 8, 8, 8, 8, true><<<BT / 8, 256, SM_E3>>>(e2, ew3, eb3, e3);
    // 5) d2 = relu(conv [up(e3), e2] 48->16 @16)
    conv_up_k<32, 16, 16, 4, 16, 2, 8, false><<<BT / 2, 256, SM_D2>>>(
        e3, e2, dw2, db2, nullptr, nullptr, nullptr, d2v);
    // 6) d1 conv + 1x1 + softmax + masked features, fused -> feat
    conv_up_k<16, 8, 8, 8, 32, 2, 8, true><<<BT / 2, 256, SM_D1>>>(
        d2v, e1, dw1, db1, xt, ow, ob, feat);
    // 7) h1-partials = feat @ lw1 via split-K x8, tf32 mma.sync (BK32, dbuf)
    sgemm1_k<<<dim3(4, BT / 128, SPLITS), 256>>>(feat, lw1, part);
    // 8) h2 = relu(relu(lb1 + sum parts) @ lw2 + lb2)
    sgemm2_k<<<dim3(4, BT / 64), 256>>>(part, lb1, lw2, lb2, h2);
    // 9) out = tanh(h2 @ lw3 + lb3)*16+16
    loc3_kernel<<<(BT * 4 + 255) / 256, 256>>>(h2, lw3, lb3, out);
}

// round 15
// speedup vs baseline: 1.0296x; 1.0296x over previous
#include <cuda_runtime.h>
#include <cuda_bf16.h>
#include <math.h>

#define BB 32
#define TT 64
#define BT 2048
#define HID 200
#define FEAT 6144
#define SPLITS 8

// -------------------- scratch (device globals; no allocs) --------------------
__device__ float g_xt  [BT * 3  * 1024];
__device__ float g_e1  [BT * 8  * 1024];
__device__ float g_e2  [BT * 16 * 256];
__device__ float g_e3  [BT * 32 * 64];
__device__ float g_d2  [BT * 16 * 256];
__device__ float g_feat[BT * FEAT];
__device__ float g_h2  [BT * HID];
__device__ float g_part[SPLITS * BT * HID];

// -------------------- permute [B,C,H,W,T] -> [B*T,C,H,W] --------------------
__global__ void permute_kernel(const float* __restrict__ x, float* __restrict__ xt) {
    int bidx = blockIdx.x;
    int h = bidx & 31;
    int c = (bidx >> 5) % 3;
    int b = bidx / 96;
    __shared__ float s[32][65];
    const float* src = x + (size_t)(((b * 3 + c) * 32 + h) * 32) * 64;
    for (int i = threadIdx.x; i < 2048; i += blockDim.x) {
        int w = i >> 6, t = i & 63;
        s[w][t] = src[i];
    }
    __syncthreads();
    for (int i = threadIdx.x; i < 2048; i += blockDim.x) {
        int t = i >> 5, w = i & 31;
        xt[((size_t)((b * 64 + t) * 3 + c) << 10) + (h << 5) + w] = s[w][t];
    }
}

// -------------------- standard conv3x3 (+optional 2x2 maxpool of input, +ReLU)
template<int CA, int COUT, int COUT_T, int HS, int NBT, int NPIX, bool POOL>
__global__ void __launch_bounds__(256, 2)
conv_std_k(const float* __restrict__ inA, const float* __restrict__ wgt,
           const float* __restrict__ bias, float* __restrict__ out)
{
    constexpr int GP   = COUT / COUT_T;
    constexpr int PXT  = HS * HS / NPIX;
    constexpr int HP   = HS + 1;
    constexpr int CSZ  = HS * HP;
    constexpr int ASZP = CA * CSZ;
    constexpr int WSZ  = COUT * CA * 9;
    extern __shared__ float sm[];
    float* sW  = sm;
    float* sBi = sW + WSZ;
    float* sIn = sBi + COUT;

    const int tid = threadIdx.x, NT = blockDim.x;
    const int bt0 = blockIdx.x * NBT;

    for (int i = tid; i < WSZ; i += NT) {
        int co = i % COUT;
        int rest = i / COUT;
        int ci = rest / 9, kk = rest % 9;
        sW[i] = wgt[(co * CA + ci) * 9 + kk];
    }
    for (int i = tid; i < COUT; i += NT) sBi[i] = bias[i];

    if (POOL) {
        for (int i = tid; i < NBT * CA * HS * HS / 2; i += NT) {
            int e2 = i * 2;
            int nn = e2 / (CA * HS * HS), rr = e2 % (CA * HS * HS);
            int c = rr / (HS * HS), pp = rr % (HS * HS);
            int hh = pp / HS, ww = pp % HS;
            const float* s = inA + (size_t)((bt0 + nn) * CA + c) * (4 * HS * HS)
                                 + (2 * hh) * (2 * HS) + 2 * ww;
            float4 r0 = *reinterpret_cast<const float4*>(s);
            float4 r1 = *reinterpret_cast<const float4*>(s + 2 * HS);
            float* d = sIn + nn * ASZP + c * CSZ + hh * HP + ww;
            d[0] = fmaxf(fmaxf(r0.x, r0.y), fmaxf(r1.x, r1.y));
            d[1] = fmaxf(fmaxf(r0.z, r0.w), fmaxf(r1.z, r1.w));
        }
    } else {
        for (int i = tid; i < NBT * CA * HS * HS / 4; i += NT) {
            int e4 = i * 4;
            int nn = e4 / (CA * HS * HS), rr = e4 % (CA * HS * HS);
            int c = rr / (HS * HS), pp = rr % (HS * HS);
            int hh = pp / HS, ww = pp % HS;
            float4 v = *reinterpret_cast<const float4*>(
                inA + (size_t)(bt0 + nn) * (CA * HS * HS) + rr);
            float* d = sIn + nn * ASZP + c * CSZ + hh * HP + ww;
            d[0] = v.x; d[1] = v.y; d[2] = v.z; d[3] = v.w;
        }
    }
    __syncthreads();

    const int n   = tid / (GP * PXT);
    const int r   = tid % (GP * PXT);
    const int cog = r / PXT;
    const int p   = r % PXT;
    const int h   = p / (HS / NPIX);
    const int w0  = (p % (HS / NPIX)) * NPIX;
    const float* sI = sIn + n * ASZP;

    float acc[COUT_T][NPIX];
    #pragma unroll
    for (int co = 0; co < COUT_T; co++) {
        float b = sBi[cog * COUT_T + co];
        #pragma unroll
        for (int j = 0; j < NPIX; j++) acc[co][j] = b;
    }

    #pragma unroll 1
    for (int ci = 0; ci < CA; ci++) {
        const float* ch = sI + ci * CSZ;
        #pragma unroll
        for (int kh = 0; kh < 3; kh++) {
            int ih = h + kh - 1;
            bool rowok = (ih >= 0) && (ih < HS);
            float v[NPIX + 2];
            #pragma unroll
            for (int j = 0; j < NPIX + 2; j++) {
                int iw = w0 + j - 1;
                v[j] = (rowok && iw >= 0 && iw < HS) ? ch[ih * HP + iw] : 0.f;
            }
            const float* wr = sW + (ci * 9 + kh * 3) * COUT + cog * COUT_T;
            #pragma unroll
            for (int co = 0; co < COUT_T; co++) {
                float wa = wr[co], wb = wr[COUT + co], wc = wr[2 * COUT + co];
                #pragma unroll
                for (int j = 0; j < NPIX; j++)
                    acc[co][j] = fmaf(wa, v[j], fmaf(wb, v[j + 1], fmaf(wc, v[j + 2], acc[co][j])));
            }
        }
    }

    const int btn = bt0 + n;
    #pragma unroll
    for (int co = 0; co < COUT_T; co++) {
        float* op = out + (size_t)((btn * COUT + cog * COUT_T + co) * HS + h) * HS + w0;
        #pragma unroll
        for (int j = 0; j < NPIX; j += 4)
            *reinterpret_cast<float4*>(op + j) =
                make_float4(fmaxf(acc[co][j], 0.f), fmaxf(acc[co][j + 1], 0.f),
                            fmaxf(acc[co][j + 2], 0.f), fmaxf(acc[co][j + 3], 0.f));
    }
}

// -------------------- decoder conv3x3 over [up2x(A), B] (+opt fused mask) ----
// A-part weights parity-folded ONCE into SMEM (both h-parities); B raw weights.
template<int CA, int CB, int COUT, int COUT_T, int HS, int NBT, int NPIX, bool FUSE>
__global__ void __launch_bounds__(256, 2)
conv_up_k(const float* __restrict__ inA, const float* __restrict__ inB,
          const float* __restrict__ wgt, const float* __restrict__ bias,
          const float* __restrict__ xtp, const float* __restrict__ owp,
          const float* __restrict__ obp, float* __restrict__ out)
{
    constexpr int CIN  = CA + CB;
    constexpr int HA   = HS / 2;
    constexpr int HAP  = HA + 1;
    constexpr int HP   = HS + 1;
    constexpr int CASZ = HA * HAP;
    constexpr int CBSZ = HS * HP;
    constexpr int ASZP = CA * CASZ;
    constexpr int TSZ  = ASZP + CB * CBSZ;
    constexpr int GP   = COUT / COUT_T;
    constexpr int PXT  = HS * HS / NPIX;
    constexpr int WBSZ = CB * 9 * COUT;
    constexpr int WFSZ = 2 * CA * 8 * COUT;
    constexpr int NC   = NPIX / 2 + 2;

    extern __shared__ float sm[];
    float* sWB = sm;                  // [CB*9][COUT]
    float* sWF = sWB + WBSZ;          // [par][ci][8][COUT]
    float* sBi = sWF + WFSZ;
    float* sOW = sBi + COUT;
    float* sIn = sOW + 18;

    const int tid = threadIdx.x, NT = blockDim.x;
    const int bt0 = blockIdx.x * NBT;

    for (int i = tid; i < WBSZ; i += NT) {
        int co = i % COUT;
        int rest = i / COUT;
        int ci = rest / 9, kk = rest % 9;
        sWB[i] = wgt[(co * CIN + CA + ci) * 9 + kk];
    }
    for (int i = tid; i < WFSZ; i += NT) {
        int co  = i % COUT;
        int t   = (i / COUT) % 8;
        int ci  = (i / (COUT * 8)) % CA;
        int par = i / (COUT * 8 * CA);
        const float* wp = wgt + (co * CIN + ci) * 9;
        float w00 = wp[0], w01 = wp[1], w02 = wp[2];
        float w10 = wp[3], w11 = wp[4], w12 = wp[5];
        float w20 = wp[6], w21 = wp[7], w22 = wp[8];
        float rA0 = par ? (w00 + w10) : w00;
        float rA1 = par ? (w01 + w11) : w01;
        float rA2 = par ? (w02 + w12) : w02;
        float rB0 = par ? w20 : (w10 + w20);
        float rB1 = par ? w21 : (w11 + w21);
        float rB2 = par ? w22 : (w12 + w22);
        float v;
        switch (t) {
            case 0: v = rA0;        break;
            case 1: v = rA0 + rA1;  break;
            case 2: v = rA1 + rA2;  break;
            case 3: v = rA2;        break;
            case 4: v = rB0;        break;
            case 5: v = rB0 + rB1;  break;
            case 6: v = rB1 + rB2;  break;
            default: v = rB2;       break;
        }
        sWF[i] = v;
    }
    for (int i = tid; i < COUT; i += NT) sBi[i] = bias[i];
    if (FUSE) {
        for (int i = tid; i < 18; i += NT) sOW[i] = (i < 16) ? owp[i] : obp[i - 16];
    }
    for (int i = tid; i < NBT * CA * HA * HA / 4; i += NT) {
        int e4 = i * 4;
        int nn = e4 / (CA * HA * HA), rr = e4 % (CA * HA * HA);
        int c = rr / (HA * HA), pp = rr % (HA * HA);
        float4 v = *reinterpret_cast<const float4*>(
            inA + (size_t)(bt0 + nn) * (CA * HA * HA) + rr);
        float* d = sIn + nn * TSZ + c * CASZ + (pp / HA) * HAP + (pp % HA);
        d[0] = v.x; d[1] = v.y; d[2] = v.z; d[3] = v.w;
    }
    for (int i = tid; i < NBT * CB * HS * HS / 4; i += NT) {
        int e4 = i * 4;
        int nn = e4 / (CB * HS * HS), rr = e4 % (CB * HS * HS);
        int c = rr / (HS * HS), pp = rr % (HS * HS);
        float4 v = *reinterpret_cast<const float4*>(
            inB + (size_t)(bt0 + nn) * (CB * HS * HS) + rr);
        float* d = sIn + nn * TSZ + ASZP + c * CBSZ + (pp / HS) * HP + (pp % HS);
        d[0] = v.x; d[1] = v.y; d[2] = v.z; d[3] = v.w;
    }
    __syncthreads();

    const int n   = tid / (GP * PXT);
    const int r   = tid % (GP * PXT);
    const int cog = r / PXT;
    const int p   = r % PXT;
    const int h   = p / (HS / NPIX);
    const int w0  = (p % (HS / NPIX)) * NPIX;
    const float* sI = sIn + n * TSZ;

    float acc[COUT_T][NPIX];
    #pragma unroll
    for (int co = 0; co < COUT_T; co++) {
        float b = sBi[cog * COUT_T + co];
        #pragma unroll
        for (int j = 0; j < NPIX; j++) acc[co][j] = b;
    }

    const int  a    = h >> 1;
    const bool hodd = (h & 1) != 0;
    const int  rowA = hodd ? a : a - 1;
    const int  rowB = hodd ? a + 1 : a;
    const int  cs0  = (w0 >> 1) - 1;
    const float* sWFp = sWF + (hodd ? CA * 8 * COUT : 0);

    #pragma unroll 1
    for (int ci = 0; ci < CA; ci++) {
        const float* ch = sI + ci * CASZ;
        float cAr[NC], cBr[NC];
        #pragma unroll
        for (int k = 0; k < NC; k++) {
            int cc = cs0 + k;
            bool cok = (cc >= 0) && (cc < HA);
            cAr[k] = (cok && rowA >= 0) ? ch[rowA * HAP + cc] : 0.f;
            cBr[k] = (cok && rowB < HA) ? ch[rowB * HAP + cc] : 0.f;
        }
        const float* wf = sWFp + ci * 8 * COUT + cog * COUT_T;
        #pragma unroll
        for (int co = 0; co < COUT_T; co++) {
            float sA0  = wf[0 * COUT + co];
            float sA01 = wf[1 * COUT + co];
            float sA12 = wf[2 * COUT + co];
            float sA2  = wf[3 * COUT + co];
            float sB0  = wf[4 * COUT + co];
            float sB01 = wf[5 * COUT + co];
            float sB12 = wf[6 * COUT + co];
            float sB2  = wf[7 * COUT + co];
            #pragma unroll
            for (int j = 0; j < NPIX; j++) {
                int lb = (j >> 1) + 1;
                if ((j & 1) == 0) {
                    acc[co][j] = fmaf(cAr[lb - 1], sA0,  acc[co][j]);
                    acc[co][j] = fmaf(cAr[lb],     sA12, acc[co][j]);
                    acc[co][j] = fmaf(cBr[lb - 1], sB0,  acc[co][j]);
                    acc[co][j] = fmaf(cBr[lb],     sB12, acc[co][j]);
                } else {
                    acc[co][j] = fmaf(cAr[lb],     sA01, acc[co][j]);
                    acc[co][j] = fmaf(cAr[lb + 1], sA2,  acc[co][j]);
                    acc[co][j] = fmaf(cBr[lb],     sB01, acc[co][j]);
                    acc[co][j] = fmaf(cBr[lb + 1], sB2,  acc[co][j]);
                }
            }
        }
    }

    #pragma unroll 1
    for (int ci = 0; ci < CB; ci++) {
        const float* ch = sI + ASZP + ci * CBSZ;
        #pragma unroll
        for (int kh = 0; kh < 3; kh++) {
            int ih = h + kh - 1;
            bool rowok = (ih >= 0) && (ih < HS);
            float v[NPIX + 2];
            #pragma unroll
            for (int j = 0; j < NPIX + 2; j++) {
                int iw = w0 + j - 1;
                v[j] = (rowok && iw >= 0 && iw < HS) ? ch[ih * HP + iw] : 0.f;
            }
            const float* wr = sWB + (ci * 9 + kh * 3) * COUT + cog * COUT_T;
            #pragma unroll
            for (int co = 0; co < COUT_T; co++) {
                float wa = wr[co], wb = wr[COUT + co], wc = wr[2 * COUT + co];
                #pragma unroll
                for (int j = 0; j < NPIX; j++)
                    acc[co][j] = fmaf(wa, v[j], fmaf(wb, v[j + 1], fmaf(wc, v[j + 2], acc[co][j])));
            }
        }
    }

    const int btn = bt0 + n;
    if constexpr (FUSE) {
        float m0a[NPIX], m1a[NPIX];
        #pragma unroll
        for (int j = 0; j < NPIX; j++) {
            float l0 = sOW[16], l1 = sOW[17];
            #pragma unroll
            for (int co = 0; co < COUT_T; co++) {
                float dv = fmaxf(acc[co][j], 0.f);
                l0 = fmaf(dv, sOW[co], l0);
                l1 = fmaf(dv, sOW[8 + co], l1);
            }
            float mx = fmaxf(fmaxf(l0, l1), 1.0f);
            float e0 = expf(l0 - mx), e1v = expf(l1 - mx), e2v = expf(1.0f - mx);
            float inv = 1.0f / (e0 + e1v + e2v);
            m0a[j] = e0 * inv;
            m1a[j] = e1v * inv;
        }
        const float* xp = xtp + ((size_t)btn * 3 << 10) + (h << 5) + w0;
        float* fp = out + (size_t)btn * FEAT + (h << 5) + w0;
        #pragma unroll
        for (int c = 0; c < 3; c++) {
            float4 xa = *reinterpret_cast<const float4*>(xp + ((size_t)c << 10));
            float4 xb = *reinterpret_cast<const float4*>(xp + ((size_t)c << 10) + 4);
            float* f0 = fp + ((size_t)c << 10);
            float* f1 = fp + ((size_t)(3 + c) << 10);
            *reinterpret_cast<float4*>(f0) =
                make_float4(m0a[0] * xa.x, m0a[1] * xa.y, m0a[2] * xa.z, m0a[3] * xa.w);
            *reinterpret_cast<float4*>(f0 + 4) =
                make_float4(m0a[4] * xb.x, m0a[5] * xb.y, m0a[6] * xb.z, m0a[7] * xb.w);
            *reinterpret_cast<float4*>(f1) =
                make_float4(m1a[0] * xa.x, m1a[1] * xa.y, m1a[2] * xa.z, m1a[3] * xa.w);
            *reinterpret_cast<float4*>(f1 + 4) =
                make_float4(m1a[4] * xb.x, m1a[5] * xb.y, m1a[6] * xb.z, m1a[7] * xb.w);
        }
    } else {
        #pragma unroll
        for (int co = 0; co < COUT_T; co++) {
            float* op = out + (size_t)((btn * COUT + cog * COUT_T + co) * HS + h) * HS + w0;
            #pragma unroll
            for (int j = 0; j < NPIX; j += 4)
                *reinterpret_cast<float4*>(op + j) =
                    make_float4(fmaxf(acc[co][j], 0.f), fmaxf(acc[co][j + 1], 0.f),
                                fmaxf(acc[co][j + 2], 0.f), fmaxf(acc[co][j + 3], 0.f));
        }
    }
}

// -------------------- GEMM1: split-K, tf32 mma.sync (m16n8k8), BK16 ----------
__device__ __forceinline__ unsigned f2tf(float f) {
    unsigned r;
    asm("cvt.rna.tf32.f32 %0, %1;" : "=r"(r) : "f"(f));
    return r;
}

__global__ void __launch_bounds__(256)
sgemm1_k(const float* __restrict__ A, const float* __restrict__ Bm,
         float* __restrict__ Cpart)
{
    constexpr int M = BT, N = HID, K = FEAT;
    constexpr int BM = 128, BN = 64, BK = 16;
    constexpr int KS = K / SPLITS;                 // 768
    constexpr int SAP = BM + 8;                    // 136
    constexpr int SBP = BN + 8;                    // 72

    __shared__ float sA[BK][SAP];
    __shared__ float sB[BK][SBP];

    const int tid  = threadIdx.x;
    const int warp = tid >> 5;
    const int lane = tid & 31;
    const int gid  = lane >> 2;
    const int tig  = lane & 3;
    const int wm   = warp & 3;
    const int wn   = warp >> 2;
    const int m_w  = wm * 32;
    const int n_w  = wn * 32;

    const int bm = blockIdx.y * BM;
    const int bn = blockIdx.x * BN;
    const int kbase = blockIdx.z * KS;

    const int c4 = tid & 3;
    const int r0 = tid >> 2;

    float c[2][4][4];
    #pragma unroll
    for (int mi = 0; mi < 2; mi++)
        #pragma unroll
        for (int ni = 0; ni < 4; ni++)
            #pragma unroll
            for (int f = 0; f < 4; f++) c[mi][ni][f] = 0.f;

    for (int k0 = kbase; k0 < kbase + KS; k0 += BK) {
        #pragma unroll
        for (int q = 0; q < 2; q++) {
            int rr = r0 + 64 * q;
            float4 av = *reinterpret_cast<const float4*>(&A[(size_t)(bm + rr) * K + k0 + c4 * 4]);
            sA[c4 * 4 + 0][rr] = __uint_as_float(f2tf(av.x));
            sA[c4 * 4 + 1][rr] = __uint_as_float(f2tf(av.y));
            sA[c4 * 4 + 2][rr] = __uint_as_float(f2tf(av.z));
            sA[c4 * 4 + 3][rr] = __uint_as_float(f2tf(av.w));
        }
        {
            int kk = tid >> 4;
            int cc = (tid & 15) * 4;
            int gcol = bn + cc;
            float b0 = (gcol + 0 < N) ? Bm[(size_t)(k0 + kk) * N + gcol + 0] : 0.f;
            float b1 = (gcol + 1 < N) ? Bm[(size_t)(k0 + kk) * N + gcol + 1] : 0.f;
            float b2 = (gcol + 2 < N) ? Bm[(size_t)(k0 + kk) * N + gcol + 2] : 0.f;
            float b3 = (gcol + 3 < N) ? Bm[(size_t)(k0 + kk) * N + gcol + 3] : 0.f;
            sB[kk][cc + 0] = __uint_as_float(f2tf(b0));
            sB[kk][cc + 1] = __uint_as_float(f2tf(b1));
            sB[kk][cc + 2] = __uint_as_float(f2tf(b2));
            sB[kk][cc + 3] = __uint_as_float(f2tf(b3));
        }
        __syncthreads();

        #pragma unroll
        for (int kc = 0; kc < BK; kc += 8) {
            unsigned bf[4][2];
            #pragma unroll
            for (int ni = 0; ni < 4; ni++) {
                bf[ni][0] = __float_as_uint(sB[kc + tig][n_w + ni * 8 + gid]);
                bf[ni][1] = __float_as_uint(sB[kc + tig + 4][n_w + ni * 8 + gid]);
            }
            #pragma unroll
            for (int mi = 0; mi < 2; mi++) {
                int mrow = m_w + mi * 16 + gid;
                unsigned a0 = __float_as_uint(sA[kc + tig][mrow]);
                unsigned a1 = __float_as_uint(sA[kc + tig][mrow + 8]);
                unsigned a2 = __float_as_uint(sA[kc + tig + 4][mrow]);
                unsigned a3 = __float_as_uint(sA[kc + tig + 4][mrow + 8]);
                #pragma unroll
                for (int ni = 0; ni < 4; ni++) {
                    asm volatile(
                        "mma.sync.aligned.m16n8k8.row.col.f32.tf32.tf32.f32 "
                        "{%0,%1,%2,%3}, {%4,%5,%6,%7}, {%8,%9}, {%0,%1,%2,%3};"
                        : "+f"(c[mi][ni][0]), "+f"(c[mi][ni][1]),
                          "+f"(c[mi][ni][2]), "+f"(c[mi][ni][3])
                        : "r"(a0), "r"(a1), "r"(a2), "r"(a3),
                          "r"(bf[ni][0]), "r"(bf[ni][1]));
                }
            }
        }
        __syncthreads();
    }

    float* Cp = Cpart + (size_t)blockIdx.z * M * N;
    #pragma unroll
    for (int mi = 0; mi < 2; mi++) {
        int row0 = bm + m_w + mi * 16 + gid;
        #pragma unroll
        for (int ni = 0; ni < 4; ni++) {
            int col0 = bn + n_w + ni * 8 + 2 * tig;
            if (col0 < N) {
                Cp[(size_t)row0 * N + col0]       = c[mi][ni][0];
                Cp[(size_t)(row0 + 8) * N + col0] = c[mi][ni][2];
            }
            if (col0 + 1 < N) {
                Cp[(size_t)row0 * N + col0 + 1]       = c[mi][ni][1];
                Cp[(size_t)(row0 + 8) * N + col0 + 1] = c[mi][ni][3];
            }
        }
    }
}

// -------------------- GEMM2 with fused split-K reduce of h1 ------------------
__global__ void __launch_bounds__(256)
sgemm2_k(const float* __restrict__ part, const float* __restrict__ ab,
         const float* __restrict__ Bm, const float* __restrict__ bias,
         float* __restrict__ C)
{
    constexpr int M = BT, N = HID, K = HID;
    constexpr int BM = 64, BN = 64, BK = 16;
    __shared__ float sA[BK][BM + 1];
    __shared__ float sB[BK][BN];
    const int tid = threadIdx.x;
    const int tx = tid % 16;
    const int ty = tid / 16;
    const int bm = blockIdx.y * BM;
    const int bn = blockIdx.x * BN;

    float acc[4][4];
    #pragma unroll
    for (int i = 0; i < 4; i++)
        #pragma unroll
        for (int j = 0; j < 4; j++) acc[i][j] = 0.f;

    for (int k0 = 0; k0 < K; k0 += BK) {
        for (int i = tid; i < BM * BK; i += 256) {
            int m = i / BK, kk = i % BK;
            float v = 0.f;
            if (k0 + kk < K) {
                size_t off = (size_t)(bm + m) * K + k0 + kk;
                float t = ab[k0 + kk];
                #pragma unroll
                for (int s = 0; s < SPLITS; s++) t += part[(size_t)s * M * K + off];
                v = fmaxf(t, 0.f);
            }
            sA[kk][m] = v;
        }
        for (int i = tid; i < BK * BN; i += 256) {
            int kk = i / BN, n = i % BN;
            sB[kk][n] = (k0 + kk < K && bn + n < N) ? Bm[(size_t)(k0 + kk) * N + bn + n] : 0.f;
        }
        __syncthreads();
        #pragma unroll
        for (int kk = 0; kk < BK; kk++) {
            float a[4], b[4];
            #pragma unroll
            for (int i = 0; i < 4; i++) a[i] = sA[kk][ty * 4 + i];
            #pragma unroll
            for (int j = 0; j < 4; j++) b[j] = sB[kk][tx * 4 + j];
            #pragma unroll
            for (int i = 0; i < 4; i++)
                #pragma unroll
                for (int j = 0; j < 4; j++) acc[i][j] = fmaf(a[i], b[j], acc[i][j]);
        }
        __syncthreads();
    }

    #pragma unroll
    for (int i = 0; i < 4; i++) {
        int m = bm + ty * 4 + i;
        #pragma unroll
        for (int j = 0; j < 4; j++) {
            int n = bn + tx * 4 + j;
            if (n >= N) continue;
            C[(size_t)m * N + n] = fmaxf(acc[i][j] + bias[n], 0.f);
        }
    }
}

// -------------------- final 200->4 + tanh scale ------------------------------
__global__ void loc3_kernel(const float* __restrict__ h2, const float* __restrict__ w3,
                            const float* __restrict__ b3, float* __restrict__ out)
{
    int idx = blockIdx.x * blockDim.x + threadIdx.x;
    if (idx >= BT * 4) return;
    int m = idx >> 2, j = idx & 3;
    float acc = b3[j];
    const float* hp = h2 + (size_t)m * HID;
    #pragma unroll 8
    for (int k = 0; k < HID; k++) acc = fmaf(hp[k], w3[k * 4 + j], acc);
    out[idx] = tanhf(acc) * 16.f + 16.f;
}

// -------------------- launch --------------------------------------------------
extern "C" void kernel_launch(void* const* d_in, const int* in_sizes, int n_in,
                              void* d_out, int out_size)
{
    const float* x   = (const float*)d_in[0];
    const float* ew1 = (const float*)d_in[1];
    const float* eb1 = (const float*)d_in[2];
    const float* ew2 = (const float*)d_in[3];
    const float* eb2 = (const float*)d_in[4];
    const float* ew3 = (const float*)d_in[5];
    const float* eb3 = (const float*)d_in[6];
    const float* dw2 = (const float*)d_in[7];
    const float* db2 = (const float*)d_in[8];
    const float* dw1 = (const float*)d_in[9];
    const float* db1 = (const float*)d_in[10];
    const float* ow  = (const float*)d_in[11];
    const float* ob  = (const float*)d_in[12];
    const float* lw1 = (const float*)d_in[13];
    const float* lb1 = (const float*)d_in[14];
    const float* lw2 = (const float*)d_in[15];
    const float* lb2 = (const float*)d_in[16];
    const float* lw3 = (const float*)d_in[17];
    const float* lb3 = (const float*)d_in[18];
    float* out = (float*)d_out;

    float *xt, *e1, *e2, *e3, *d2v, *feat, *h2, *part;
    cudaGetSymbolAddress((void**)&xt,   g_xt);
    cudaGetSymbolAddress((void**)&e1,   g_e1);
    cudaGetSymbolAddress((void**)&e2,   g_e2);
    cudaGetSymbolAddress((void**)&e3,   g_e3);
    cudaGetSymbolAddress((void**)&d2v,  g_d2);
    cudaGetSymbolAddress((void**)&feat, g_feat);
    cudaGetSymbolAddress((void**)&h2,   g_h2);
    cudaGetSymbolAddress((void**)&part, g_part);

    constexpr int SM_E1 = (3 * 8 * 9  + 8  + 2 * 3 * 32 * 33) * 4;
    constexpr int SM_E2 = (8 * 16 * 9 + 16 + 4 * 8 * 16 * 17) * 4;
    constexpr int SM_E3 = (16 * 32 * 9 + 32 + 8 * 16 * 8 * 9) * 4;
    constexpr int SM_D2 = (16 * 9 * 16 + 2 * 32 * 8 * 16 + 16 + 18
                           + 2 * (32 * 8 * 9 + 16 * 16 * 17)) * 4;     // 95368
    constexpr int SM_D1 = (8 * 9 * 8 + 2 * 16 * 8 * 8 + 8 + 18
                           + 2 * (16 * 16 * 17 + 8 * 32 * 33)) * 4;    // 113000

    cudaFuncSetAttribute((const void*)conv_std_k<8, 16, 8, 16, 4, 8, true>,
                         cudaFuncAttributeMaxDynamicSharedMemorySize, SM_E2);
    cudaFuncSetAttribute((const void*)conv_std_k<16, 32, 8, 8, 8, 8, true>,
                         cudaFuncAttributeMaxDynamicSharedMemorySize, SM_E3);
    cudaFuncSetAttribute((const void*)conv_up_k<32, 16, 16, 4, 16, 2, 8, false>,
                         cudaFuncAttributeMaxDynamicSharedMemorySize, SM_D2);
    cudaFuncSetAttribute((const void*)conv_up_k<16, 8, 8, 8, 32, 2, 8, true>,
                         cudaFuncAttributeMaxDynamicSharedMemorySize, SM_D1);

    // 1) permute
    permute_kernel<<<32 * 3 * 32, 256>>>(x, xt);
    // 2) e1 = relu(conv 3->8 @32)
    conv_std_k<3, 8, 8, 32, 2, 8, false><<<BT / 2, 256, SM_E1>>>(xt, ew1, eb1, e1);
    // 3) e2 = relu(conv pool(e1) 8->16 @16)
    conv_std_k<8, 16, 8, 16, 4, 8, true><<<BT / 4, 256, SM_E2>>>(e1, ew2, eb2, e2);
    // 4) e3 = relu(conv pool(e2) 16->32 @8)
    conv_std_k<16, 32, 8, 8, 8, 8, true><<<BT / 8, 256, SM_E3>>>(e2, ew3, eb3, e3);
    // 5) d2 = relu(conv [up(e3), e2] 48->16 @16)
    conv_up_k<32, 16, 16, 4, 16, 2, 8, false><<<BT / 2, 256, SM_D2>>>(
        e3, e2, dw2, db2, nullptr, nullptr, nullptr, d2v);
    // 6) d1 conv + 1x1 + softmax + masked features, fused -> feat
    conv_up_k<16, 8, 8, 8, 32, 2, 8, true><<<BT / 2, 256, SM_D1>>>(
        d2v, e1, dw1, db1, xt, ow, ob, feat);
    // 7) h1-partials = feat @ lw1 via split-K x8, tf32 mma.sync (R13 BK16 form)
    sgemm1_k<<<dim3(4, BT / 128, SPLITS), 256>>>(feat, lw1, part);
    // 8) h2 = relu(relu(lb1 + sum parts) @ lw2 + lb2)
    sgemm2_k<<<dim3(4, BT / 64), 256>>>(part, lb1, lw2, lb2, h2);
    // 9) out = tanh(h2 @ lw3 + lb3)*16+16
    loc3_kernel<<<(BT * 4 + 255) / 256, 256>>>(h2, lw3, lb3, out);
}

// round 16
// speedup vs baseline: 1.0730x; 1.0421x over previous
#include <cuda_runtime.h>
#include <cuda_bf16.h>
#include <math.h>

#define BB 32
#define TT 64
#define BT 2048
#define HID 200
#define FEAT 6144
#define SPLITS 4

// -------------------- scratch (device globals; no allocs) --------------------
__device__ float g_xt  [BT * 3  * 1024];
__device__ float g_e1  [BT * 8  * 1024];
__device__ float g_e2  [BT * 16 * 256];
__device__ float g_e3  [BT * 32 * 64];
__device__ float g_d2  [BT * 16 * 256];
__device__ float g_feat[BT * FEAT];
__device__ float g_h2  [BT * HID];
__device__ float g_part[SPLITS * BT * HID];

// -------------------- permute [B,C,H,W,T] -> [B*T,C,H,W] --------------------
__global__ void permute_kernel(const float* __restrict__ x, float* __restrict__ xt) {
    int bidx = blockIdx.x;
    int h = bidx & 31;
    int c = (bidx >> 5) % 3;
    int b = bidx / 96;
    __shared__ float s[32][65];
    const float* src = x + (size_t)(((b * 3 + c) * 32 + h) * 32) * 64;
    for (int i = threadIdx.x; i < 2048; i += blockDim.x) {
        int w = i >> 6, t = i & 63;
        s[w][t] = src[i];
    }
    __syncthreads();
    for (int i = threadIdx.x; i < 2048; i += blockDim.x) {
        int t = i >> 5, w = i & 31;
        xt[((size_t)((b * 64 + t) * 3 + c) << 10) + (h << 5) + w] = s[w][t];
    }
}

// -------------------- standard conv3x3 (+optional 2x2 maxpool of input, +ReLU)
template<int CA, int COUT, int COUT_T, int HS, int NBT, int NPIX, bool POOL>
__global__ void __launch_bounds__(256, 2)
conv_std_k(const float* __restrict__ inA, const float* __restrict__ wgt,
           const float* __restrict__ bias, float* __restrict__ out)
{
    constexpr int GP   = COUT / COUT_T;
    constexpr int PXT  = HS * HS / NPIX;
    constexpr int HP   = HS + 1;
    constexpr int CSZ  = HS * HP;
    constexpr int ASZP = CA * CSZ;
    constexpr int WSZ  = COUT * CA * 9;
    extern __shared__ float sm[];
    float* sW  = sm;
    float* sBi = sW + WSZ;
    float* sIn = sBi + COUT;

    const int tid = threadIdx.x, NT = blockDim.x;
    const int bt0 = blockIdx.x * NBT;

    for (int i = tid; i < WSZ; i += NT) {
        int co = i % COUT;
        int rest = i / COUT;
        int ci = rest / 9, kk = rest % 9;
        sW[i] = wgt[(co * CA + ci) * 9 + kk];
    }
    for (int i = tid; i < COUT; i += NT) sBi[i] = bias[i];

    if (POOL) {
        for (int i = tid; i < NBT * CA * HS * HS / 2; i += NT) {
            int e2 = i * 2;
            int nn = e2 / (CA * HS * HS), rr = e2 % (CA * HS * HS);
            int c = rr / (HS * HS), pp = rr % (HS * HS);
            int hh = pp / HS, ww = pp % HS;
            const float* s = inA + (size_t)((bt0 + nn) * CA + c) * (4 * HS * HS)
                                 + (2 * hh) * (2 * HS) + 2 * ww;
            float4 r0 = *reinterpret_cast<const float4*>(s);
            float4 r1 = *reinterpret_cast<const float4*>(s + 2 * HS);
            float* d = sIn + nn * ASZP + c * CSZ + hh * HP + ww;
            d[0] = fmaxf(fmaxf(r0.x, r0.y), fmaxf(r1.x, r1.y));
            d[1] = fmaxf(fmaxf(r0.z, r0.w), fmaxf(r1.z, r1.w));
        }
    } else {
        for (int i = tid; i < NBT * CA * HS * HS / 4; i += NT) {
            int e4 = i * 4;
            int nn = e4 / (CA * HS * HS), rr = e4 % (CA * HS * HS);
            int c = rr / (HS * HS), pp = rr % (HS * HS);
            int hh = pp / HS, ww = pp % HS;
            float4 v = *reinterpret_cast<const float4*>(
                inA + (size_t)(bt0 + nn) * (CA * HS * HS) + rr);
            float* d = sIn + nn * ASZP + c * CSZ + hh * HP + ww;
            d[0] = v.x; d[1] = v.y; d[2] = v.z; d[3] = v.w;
        }
    }
    __syncthreads();

    const int n   = tid / (GP * PXT);
    const int r   = tid % (GP * PXT);
    const int cog = r / PXT;
    const int p   = r % PXT;
    const int h   = p / (HS / NPIX);
    const int w0  = (p % (HS / NPIX)) * NPIX;
    const float* sI = sIn + n * ASZP;

    float acc[COUT_T][NPIX];
    #pragma unroll
    for (int co = 0; co < COUT_T; co++) {
        float b = sBi[cog * COUT_T + co];
        #pragma unroll
        for (int j = 0; j < NPIX; j++) acc[co][j] = b;
    }

    #pragma unroll 1
    for (int ci = 0; ci < CA; ci++) {
        const float* ch = sI + ci * CSZ;
        #pragma unroll
        for (int kh = 0; kh < 3; kh++) {
            int ih = h + kh - 1;
            bool rowok = (ih >= 0) && (ih < HS);
            float v[NPIX + 2];
            #pragma unroll
            for (int j = 0; j < NPIX + 2; j++) {
                int iw = w0 + j - 1;
                v[j] = (rowok && iw >= 0 && iw < HS) ? ch[ih * HP + iw] : 0.f;
            }
            const float* wr = sW + (ci * 9 + kh * 3) * COUT + cog * COUT_T;
            #pragma unroll
            for (int co = 0; co < COUT_T; co++) {
                float wa = wr[co], wb = wr[COUT + co], wc = wr[2 * COUT + co];
                #pragma unroll
                for (int j = 0; j < NPIX; j++)
                    acc[co][j] = fmaf(wa, v[j], fmaf(wb, v[j + 1], fmaf(wc, v[j + 2], acc[co][j])));
            }
        }
    }

    const int btn = bt0 + n;
    #pragma unroll
    for (int co = 0; co < COUT_T; co++) {
        float* op = out + (size_t)((btn * COUT + cog * COUT_T + co) * HS + h) * HS + w0;
        #pragma unroll
        for (int j = 0; j < NPIX; j += 4)
            *reinterpret_cast<float4*>(op + j) =
                make_float4(fmaxf(acc[co][j], 0.f), fmaxf(acc[co][j + 1], 0.f),
                            fmaxf(acc[co][j + 2], 0.f), fmaxf(acc[co][j + 3], 0.f));
    }
}

// -------------------- decoder conv3x3 over [up2x(A), B] (+opt fused mask) ----
template<int CA, int CB, int COUT, int COUT_T, int HS, int NBT, int NPIX, bool FUSE>
__global__ void __launch_bounds__(256, 2)
conv_up_k(const float* __restrict__ inA, const float* __restrict__ inB,
          const float* __restrict__ wgt, const float* __restrict__ bias,
          const float* __restrict__ xtp, const float* __restrict__ owp,
          const float* __restrict__ obp, float* __restrict__ out)
{
    constexpr int CIN  = CA + CB;
    constexpr int HA   = HS / 2;
    constexpr int HAP  = HA + 1;
    constexpr int HP   = HS + 1;
    constexpr int CASZ = HA * HAP;
    constexpr int CBSZ = HS * HP;
    constexpr int ASZP = CA * CASZ;
    constexpr int TSZ  = ASZP + CB * CBSZ;
    constexpr int GP   = COUT / COUT_T;
    constexpr int PXT  = HS * HS / NPIX;
    constexpr int WSZ  = COUT * CIN * 9;
    constexpr int NC   = NPIX / 2 + 2;

    extern __shared__ float sm[];
    float* sW  = sm;
    float* sBi = sW + WSZ;
    float* sOW = sBi + COUT;
    float* sIn = sOW + 18;

    const int tid = threadIdx.x, NT = blockDim.x;
    const int bt0 = blockIdx.x * NBT;

    for (int i = tid; i < WSZ; i += NT) {
        int co = i % COUT;
        int rest = i / COUT;
        int ci = rest / 9, kk = rest % 9;
        sW[i] = wgt[(co * CIN + ci) * 9 + kk];
    }
    for (int i = tid; i < COUT; i += NT) sBi[i] = bias[i];
    if (FUSE) {
        for (int i = tid; i < 18; i += NT) sOW[i] = (i < 16) ? owp[i] : obp[i - 16];
    }
    for (int i = tid; i < NBT * CA * HA * HA / 4; i += NT) {
        int e4 = i * 4;
        int nn = e4 / (CA * HA * HA), rr = e4 % (CA * HA * HA);
        int c = rr / (HA * HA), pp = rr % (HA * HA);
        float4 v = *reinterpret_cast<const float4*>(
            inA + (size_t)(bt0 + nn) * (CA * HA * HA) + rr);
        float* d = sIn + nn * TSZ + c * CASZ + (pp / HA) * HAP + (pp % HA);
        d[0] = v.x; d[1] = v.y; d[2] = v.z; d[3] = v.w;
    }
    for (int i = tid; i < NBT * CB * HS * HS / 4; i += NT) {
        int e4 = i * 4;
        int nn = e4 / (CB * HS * HS), rr = e4 % (CB * HS * HS);
        int c = rr / (HS * HS), pp = rr % (HS * HS);
        float4 v = *reinterpret_cast<const float4*>(
            inB + (size_t)(bt0 + nn) * (CB * HS * HS) + rr);
        float* d = sIn + nn * TSZ + ASZP + c * CBSZ + (pp / HS) * HP + (pp % HS);
        d[0] = v.x; d[1] = v.y; d[2] = v.z; d[3] = v.w;
    }
    __syncthreads();

    const int n   = tid / (GP * PXT);
    const int r   = tid % (GP * PXT);
    const int cog = r / PXT;
    const int p   = r % PXT;
    const int h   = p / (HS / NPIX);
    const int w0  = (p % (HS / NPIX)) * NPIX;
    const float* sI = sIn + n * TSZ;

    float acc[COUT_T][NPIX];
    #pragma unroll
    for (int co = 0; co < COUT_T; co++) {
        float b = sBi[cog * COUT_T + co];
        #pragma unroll
        for (int j = 0; j < NPIX; j++) acc[co][j] = b;
    }

    const int  a    = h >> 1;
    const bool hodd = (h & 1) != 0;
    const int  rowA = hodd ? a : a - 1;
    const int  rowB = hodd ? a + 1 : a;
    const int  cs0  = (w0 >> 1) - 1;

    #pragma unroll 1
    for (int ci = 0; ci < CA; ci++) {
        const float* ch = sI + ci * CASZ;
        float cAr[NC], cBr[NC];
        #pragma unroll
        for (int k = 0; k < NC; k++) {
            int cc = cs0 + k;
            bool cok = (cc >= 0) && (cc < HA);
            cAr[k] = (cok && rowA >= 0) ? ch[rowA * HAP + cc] : 0.f;
            cBr[k] = (cok && rowB < HA) ? ch[rowB * HAP + cc] : 0.f;
        }
        const float* wr = sW + ci * 9 * COUT + cog * COUT_T;
        #pragma unroll
        for (int co = 0; co < COUT_T; co++) {
            float w00 = wr[0 * COUT + co], w01 = wr[1 * COUT + co], w02 = wr[2 * COUT + co];
            float w10 = wr[3 * COUT + co], w11 = wr[4 * COUT + co], w12 = wr[5 * COUT + co];
            float w20 = wr[6 * COUT + co], w21 = wr[7 * COUT + co], w22 = wr[8 * COUT + co];
            float rA0 = hodd ? (w00 + w10) : w00;
            float rA1 = hodd ? (w01 + w11) : w01;
            float rA2 = hodd ? (w02 + w12) : w02;
            float rB0 = hodd ? w20 : (w10 + w20);
            float rB1 = hodd ? w21 : (w11 + w21);
            float rB2 = hodd ? w22 : (w12 + w22);
            float sA0 = rA0, sA01 = rA0 + rA1, sA12 = rA1 + rA2, sA2 = rA2;
            float sB0 = rB0, sB01 = rB0 + rB1, sB12 = rB1 + rB2, sB2 = rB2;
            #pragma unroll
            for (int j = 0; j < NPIX; j++) {
                int lb = (j >> 1) + 1;
                if ((j & 1) == 0) {
                    acc[co][j] = fmaf(cAr[lb - 1], sA0,  acc[co][j]);
                    acc[co][j] = fmaf(cAr[lb],     sA12, acc[co][j]);
                    acc[co][j] = fmaf(cBr[lb - 1], sB0,  acc[co][j]);
                    acc[co][j] = fmaf(cBr[lb],     sB12, acc[co][j]);
                } else {
                    acc[co][j] = fmaf(cAr[lb],     sA01, acc[co][j]);
                    acc[co][j] = fmaf(cAr[lb + 1], sA2,  acc[co][j]);
                    acc[co][j] = fmaf(cBr[lb],     sB01, acc[co][j]);
                    acc[co][j] = fmaf(cBr[lb + 1], sB2,  acc[co][j]);
                }
            }
        }
    }

    #pragma unroll 1
    for (int ci = 0; ci < CB; ci++) {
        const float* ch = sI + ASZP + ci * CBSZ;
        #pragma unroll
        for (int kh = 0; kh < 3; kh++) {
            int ih = h + kh - 1;
            bool rowok = (ih >= 0) && (ih < HS);
            float v[NPIX + 2];
            #pragma unroll
            for (int j = 0; j < NPIX + 2; j++) {
                int iw = w0 + j - 1;
                v[j] = (rowok && iw >= 0 && iw < HS) ? ch[ih * HP + iw] : 0.f;
            }
            const float* wr = sW + ((CA + ci) * 9 + kh * 3) * COUT + cog * COUT_T;
            #pragma unroll
            for (int co = 0; co < COUT_T; co++) {
                float wa = wr[co], wb = wr[COUT + co], wc = wr[2 * COUT + co];
                #pragma unroll
                for (int j = 0; j < NPIX; j++)
                    acc[co][j] = fmaf(wa, v[j], fmaf(wb, v[j + 1], fmaf(wc, v[j + 2], acc[co][j])));
            }
        }
    }

    const int btn = bt0 + n;
    if constexpr (FUSE) {
        float m0a[NPIX], m1a[NPIX];
        #pragma unroll
        for (int j = 0; j < NPIX; j++) {
            float l0 = sOW[16], l1 = sOW[17];
            #pragma unroll
            for (int co = 0; co < COUT_T; co++) {
                float dv = fmaxf(acc[co][j], 0.f);
                l0 = fmaf(dv, sOW[co], l0);
                l1 = fmaf(dv, sOW[8 + co], l1);
            }
            float mx = fmaxf(fmaxf(l0, l1), 1.0f);
            float e0 = expf(l0 - mx), e1v = expf(l1 - mx), e2v = expf(1.0f - mx);
            float inv = 1.0f / (e0 + e1v + e2v);
            m0a[j] = e0 * inv;
            m1a[j] = e1v * inv;
        }
        const float* xp = xtp + ((size_t)btn * 3 << 10) + (h << 5) + w0;
        float* fp = out + (size_t)btn * FEAT + (h << 5) + w0;
        #pragma unroll
        for (int c = 0; c < 3; c++) {
            float4 xa = *reinterpret_cast<const float4*>(xp + ((size_t)c << 10));
            float4 xb = *reinterpret_cast<const float4*>(xp + ((size_t)c << 10) + 4);
            float* f0 = fp + ((size_t)c << 10);
            float* f1 = fp + ((size_t)(3 + c) << 10);
            *reinterpret_cast<float4*>(f0) =
                make_float4(m0a[0] * xa.x, m0a[1] * xa.y, m0a[2] * xa.z, m0a[3] * xa.w);
            *reinterpret_cast<float4*>(f0 + 4) =
                make_float4(m0a[4] * xb.x, m0a[5] * xb.y, m0a[6] * xb.z, m0a[7] * xb.w);
            *reinterpret_cast<float4*>(f1) =
                make_float4(m1a[0] * xa.x, m1a[1] * xa.y, m1a[2] * xa.z, m1a[3] * xa.w);
            *reinterpret_cast<float4*>(f1 + 4) =
                make_float4(m1a[4] * xb.x, m1a[5] * xb.y, m1a[6] * xb.z, m1a[7] * xb.w);
        }
    } else {
        #pragma unroll
        for (int co = 0; co < COUT_T; co++) {
            float* op = out + (size_t)((btn * COUT + cog * COUT_T + co) * HS + h) * HS + w0;
            #pragma unroll
            for (int j = 0; j < NPIX; j += 4)
                *reinterpret_cast<float4*>(op + j) =
                    make_float4(fmaxf(acc[co][j], 0.f), fmaxf(acc[co][j + 1], 0.f),
                                fmaxf(acc[co][j + 2], 0.f), fmaxf(acc[co][j + 3], 0.f));
        }
    }
}

// -------------------- GEMM1: split-K, tf32 mma.sync (m16n8k8), BK16 ----------
__device__ __forceinline__ unsigned f2tf(float f) {
    unsigned r;
    asm("cvt.rna.tf32.f32 %0, %1;" : "=r"(r) : "f"(f));
    return r;
}

__global__ void __launch_bounds__(256)
sgemm1_k(const float* __restrict__ A, const float* __restrict__ Bm,
         float* __restrict__ Cpart)
{
    constexpr int M = BT, N = HID, K = FEAT;
    constexpr int BM = 128, BN = 64, BK = 16;
    constexpr int KS = K / SPLITS;                 // 1536
    constexpr int SAP = BM + 8;                    // 136
    constexpr int SBP = BN + 8;                    // 72

    __shared__ float sA[BK][SAP];
    __shared__ float sB[BK][SBP];

    const int tid  = threadIdx.x;
    const int warp = tid >> 5;
    const int lane = tid & 31;
    const int gid  = lane >> 2;
    const int tig  = lane & 3;
    const int wm   = warp & 3;
    const int wn   = warp >> 2;
    const int m_w  = wm * 32;
    const int n_w  = wn * 32;

    const int bm = blockIdx.y * BM;
    const int bn = blockIdx.x * BN;
    const int kbase = blockIdx.z * KS;

    const int c4 = tid & 3;
    const int r0 = tid >> 2;

    float c[2][4][4];
    #pragma unroll
    for (int mi = 0; mi < 2; mi++)
        #pragma unroll
        for (int ni = 0; ni < 4; ni++)
            #pragma unroll
            for (int f = 0; f < 4; f++) c[mi][ni][f] = 0.f;

    for (int k0 = kbase; k0 < kbase + KS; k0 += BK) {
        #pragma unroll
        for (int q = 0; q < 2; q++) {
            int rr = r0 + 64 * q;
            float4 av = *reinterpret_cast<const float4*>(&A[(size_t)(bm + rr) * K + k0 + c4 * 4]);
            sA[c4 * 4 + 0][rr] = __uint_as_float(f2tf(av.x));
            sA[c4 * 4 + 1][rr] = __uint_as_float(f2tf(av.y));
            sA[c4 * 4 + 2][rr] = __uint_as_float(f2tf(av.z));
            sA[c4 * 4 + 3][rr] = __uint_as_float(f2tf(av.w));
        }
        {
            int kk = tid >> 4;
            int cc = (tid & 15) * 4;
            int gcol = bn + cc;
            float b0 = (gcol + 0 < N) ? Bm[(size_t)(k0 + kk) * N + gcol + 0] : 0.f;
            float b1 = (gcol + 1 < N) ? Bm[(size_t)(k0 + kk) * N + gcol + 1] : 0.f;
            float b2 = (gcol + 2 < N) ? Bm[(size_t)(k0 + kk) * N + gcol + 2] : 0.f;
            float b3 = (gcol + 3 < N) ? Bm[(size_t)(k0 + kk) * N + gcol + 3] : 0.f;
            sB[kk][cc + 0] = __uint_as_float(f2tf(b0));
            sB[kk][cc + 1] = __uint_as_float(f2tf(b1));
            sB[kk][cc + 2] = __uint_as_float(f2tf(b2));
            sB[kk][cc + 3] = __uint_as_float(f2tf(b3));
        }
        __syncthreads();

        #pragma unroll
        for (int kc = 0; kc < BK; kc += 8) {
            unsigned bf[4][2];
            #pragma unroll
            for (int ni = 0; ni < 4; ni++) {
                bf[ni][0] = __float_as_uint(sB[kc + tig][n_w + ni * 8 + gid]);
                bf[ni][1] = __float_as_uint(sB[kc + tig + 4][n_w + ni * 8 + gid]);
            }
            #pragma unroll
            for (int mi = 0; mi < 2; mi++) {
                int mrow = m_w + mi * 16 + gid;
                unsigned a0 = __float_as_uint(sA[kc + tig][mrow]);
                unsigned a1 = __float_as_uint(sA[kc + tig][mrow + 8]);
                unsigned a2 = __float_as_uint(sA[kc + tig + 4][mrow]);
                unsigned a3 = __float_as_uint(sA[kc + tig + 4][mrow + 8]);
                #pragma unroll
                for (int ni = 0; ni < 4; ni++) {
                    asm volatile(
                        "mma.sync.aligned.m16n8k8.row.col.f32.tf32.tf32.f32 "
                        "{%0,%1,%2,%3}, {%4,%5,%6,%7}, {%8,%9}, {%0,%1,%2,%3};"
                        : "+f"(c[mi][ni][0]), "+f"(c[mi][ni][1]),
                          "+f"(c[mi][ni][2]), "+f"(c[mi][ni][3])
                        : "r"(a0), "r"(a1), "r"(a2), "r"(a3),
                          "r"(bf[ni][0]), "r"(bf[ni][1]));
                }
            }
        }
        __syncthreads();
    }

    float* Cp = Cpart + (size_t)blockIdx.z * M * N;
    #pragma unroll
    for (int mi = 0; mi < 2; mi++) {
        int row0 = bm + m_w + mi * 16 + gid;
        #pragma unroll
        for (int ni = 0; ni < 4; ni++) {
            int col0 = bn + n_w + ni * 8 + 2 * tig;
            if (col0 < N) {
                Cp[(size_t)row0 * N + col0]       = c[mi][ni][0];
                Cp[(size_t)(row0 + 8) * N + col0] = c[mi][ni][2];
            }
            if (col0 + 1 < N) {
                Cp[(size_t)row0 * N + col0 + 1]       = c[mi][ni][1];
                Cp[(size_t)(row0 + 8) * N + col0 + 1] = c[mi][ni][3];
            }
        }
    }
}

// -------------------- GEMM2 with fused split-K reduce of h1 ------------------
__global__ void __launch_bounds__(256)
sgemm2_k(const float* __restrict__ part, const float* __restrict__ ab,
         const float* __restrict__ Bm, const float* __restrict__ bias,
         float* __restrict__ C)
{
    constexpr int M = BT, N = HID, K = HID;
    constexpr int BM = 64, BN = 64, BK = 16;
    __shared__ float sA[BK][BM + 1];
    __shared__ float sB[BK][BN];
    const int tid = threadIdx.x;
    const int tx = tid % 16;
    const int ty = tid / 16;
    const int bm = blockIdx.y * BM;
    const int bn = blockIdx.x * BN;

    float acc[4][4];
    #pragma unroll
    for (int i = 0; i < 4; i++)
        #pragma unroll
        for (int j = 0; j < 4; j++) acc[i][j] = 0.f;

    for (int k0 = 0; k0 < K; k0 += BK) {
        for (int i = tid; i < BM * BK; i += 256) {
            int m = i / BK, kk = i % BK;
            float v = 0.f;
            if (k0 + kk < K) {
                size_t off = (size_t)(bm + m) * K + k0 + kk;
                float t = ab[k0 + kk];
                #pragma unroll
                for (int s = 0; s < SPLITS; s++) t += part[(size_t)s * M * K + off];
                v = fmaxf(t, 0.f);
            }
            sA[kk][m] = v;
        }
        for (int i = tid; i < BK * BN; i += 256) {
            int kk = i / BN, n = i % BN;
            sB[kk][n] = (k0 + kk < K && bn + n < N) ? Bm[(size_t)(k0 + kk) * N + bn + n] : 0.f;
        }
        __syncthreads();
        #pragma unroll
        for (int kk = 0; kk < BK; kk++) {
            float a[4], b[4];
            #pragma unroll
            for (int i = 0; i < 4; i++) a[i] = sA[kk][ty * 4 + i];
            #pragma unroll
            for (int j = 0; j < 4; j++) b[j] = sB[kk][tx * 4 + j];
            #pragma unroll
            for (int i = 0; i < 4; i++)
                #pragma unroll
                for (int j = 0; j < 4; j++) acc[i][j] = fmaf(a[i], b[j], acc[i][j]);
        }
        __syncthreads();
    }

    #pragma unroll
    for (int i = 0; i < 4; i++) {
        int m = bm + ty * 4 + i;
        #pragma unroll
        for (int j = 0; j < 4; j++) {
            int n = bn + tx * 4 + j;
            if (n >= N) continue;
            C[(size_t)m * N + n] = fmaxf(acc[i][j] + bias[n], 0.f);
        }
    }
}

// -------------------- final 200->4 + tanh scale ------------------------------
__global__ void loc3_kernel(const float* __restrict__ h2, const float* __restrict__ w3,
                            const float* __restrict__ b3, float* __restrict__ out)
{
    int idx = blockIdx.x * blockDim.x + threadIdx.x;
    if (idx >= BT * 4) return;
    int m = idx >> 2, j = idx & 3;
    float acc = b3[j];
    const float* hp = h2 + (size_t)m * HID;
    #pragma unroll 8
    for (int k = 0; k < HID; k++) acc = fmaf(hp[k], w3[k * 4 + j], acc);
    out[idx] = tanhf(acc) * 16.f + 16.f;
}

// -------------------- launch --------------------------------------------------
extern "C" void kernel_launch(void* const* d_in, const int* in_sizes, int n_in,
                              void* d_out, int out_size)
{
    const float* x   = (const float*)d_in[0];
    const float* ew1 = (const float*)d_in[1];
    const float* eb1 = (const float*)d_in[2];
    const float* ew2 = (const float*)d_in[3];
    const float* eb2 = (const float*)d_in[4];
    const float* ew3 = (const float*)d_in[5];
    const float* eb3 = (const float*)d_in[6];
    const float* dw2 = (const float*)d_in[7];
    const float* db2 = (const float*)d_in[8];
    const float* dw1 = (const float*)d_in[9];
    const float* db1 = (const float*)d_in[10];
    const float* ow  = (const float*)d_in[11];
    const float* ob  = (const float*)d_in[12];
    const float* lw1 = (const float*)d_in[13];
    const float* lb1 = (const float*)d_in[14];
    const float* lw2 = (const float*)d_in[15];
    const float* lb2 = (const float*)d_in[16];
    const float* lw3 = (const float*)d_in[17];
    const float* lb3 = (const float*)d_in[18];
    float* out = (float*)d_out;

    float *xt, *e1, *e2, *e3, *d2v, *feat, *h2, *part;
    cudaGetSymbolAddress((void**)&xt,   g_xt);
    cudaGetSymbolAddress((void**)&e1,   g_e1);
    cudaGetSymbolAddress((void**)&e2,   g_e2);
    cudaGetSymbolAddress((void**)&e3,   g_e3);
    cudaGetSymbolAddress((void**)&d2v,  g_d2);
    cudaGetSymbolAddress((void**)&feat, g_feat);
    cudaGetSymbolAddress((void**)&h2,   g_h2);
    cudaGetSymbolAddress((void**)&part, g_part);

    constexpr int SM_E1 = (3 * 8 * 9  + 8  + 2 * 3 * 32 * 33) * 4;
    constexpr int SM_E2 = (8 * 16 * 9 + 16 + 4 * 8 * 16 * 17) * 4;
    constexpr int SM_E3 = (16 * 32 * 9 + 32 + 8 * 16 * 8 * 9) * 4;
    constexpr int SM_D2 = (48 * 16 * 9 + 16 + 18 + 2 * (32 * 8 * 9 + 16 * 16 * 17)) * 4;
    constexpr int SM_D1 = (24 * 8 * 9 + 8 + 18 + 2 * (16 * 16 * 17 + 8 * 32 * 33)) * 4;

    cudaFuncSetAttribute((const void*)conv_std_k<8, 16, 8, 16, 4, 8, true>,
                         cudaFuncAttributeMaxDynamicSharedMemorySize, SM_E2);
    cudaFuncSetAttribute((const void*)conv_std_k<16, 32, 8, 8, 8, 8, true>,
                         cudaFuncAttributeMaxDynamicSharedMemorySize, SM_E3);
    cudaFuncSetAttribute((const void*)conv_up_k<32, 16, 16, 4, 16, 2, 8, false>,
                         cudaFuncAttributeMaxDynamicSharedMemorySize, SM_D2);
    cudaFuncSetAttribute((const void*)conv_up_k<16, 8, 8, 8, 32, 2, 8, true>,
                         cudaFuncAttributeMaxDynamicSharedMemorySize, SM_D1);

    // 1) permute
    permute_kernel<<<32 * 3 * 32, 256>>>(x, xt);
    // 2) e1 = relu(conv 3->8 @32)
    conv_std_k<3, 8, 8, 32, 2, 8, false><<<BT / 2, 256, SM_E1>>>(xt, ew1, eb1, e1);
    // 3) e2 = relu(conv pool(e1) 8->16 @16)
    conv_std_k<8, 16, 8, 16, 4, 8, true><<<BT / 4, 256, SM_E2>>>(e1, ew2, eb2, e2);
    // 4) e3 = relu(conv pool(e2) 16->32 @8)
    conv_std_k<16, 32, 8, 8, 8, 8, true><<<BT / 8, 256, SM_E3>>>(e2, ew3, eb3, e3);
    // 5) d2 = relu(conv [up(e3), e2] 48->16 @16)
    conv_up_k<32, 16, 16, 4, 16, 2, 8, false><<<BT / 2, 256, SM_D2>>>(
        e3, e2, dw2, db2, nullptr, nullptr, nullptr, d2v);
    // 6) d1 conv + 1x1 + softmax + masked features, fused -> feat
    conv_up_k<16, 8, 8, 8, 32, 2, 8, true><<<BT / 2, 256, SM_D1>>>(
        d2v, e1, dw1, db1, xt, ow, ob, feat);
    // 7) h1-partials = feat @ lw1 via split-K x4, tf32 mma.sync
    sgemm1_k<<<dim3(4, BT / 128, SPLITS), 256>>>(feat, lw1, part);
    // 8) h2 = relu(relu(lb1 + sum parts) @ lw2 + lb2)
    sgemm2_k<<<dim3(4, BT / 64), 256>>>(part, lb1, lw2, lb2, h2);
    // 9) out = tanh(h2 @ lw3 + lb3)*16+16
    loc3_kernel<<<(BT * 4 + 255) / 256, 256>>>(h2, lw3, lb3, out);
}

// round 17
// speedup vs baseline: 1.0999x; 1.0250x over previous
#include <cuda_runtime.h>
#include <cuda_bf16.h>
#include <math.h>

#define BB 32
#define TT 64
#define BT 2048
#define HID 200
#define FEAT 6144
#define SPLITS 8

// -------------------- scratch (device globals; no allocs) --------------------
__device__ float g_xt  [BT * 3  * 1024];
__device__ float g_e1  [BT * 8  * 1024];
__device__ float g_e2  [BT * 16 * 256];
__device__ float g_e3  [BT * 32 * 64];
__device__ float g_d2  [BT * 16 * 256];
__device__ float g_feat[BT * FEAT];
__device__ float g_h2  [BT * HID];
__device__ float g_part[SPLITS * BT * HID];

// -------------------- permute [B,C,H,W,T] -> [B*T,C,H,W] --------------------
__global__ void permute_kernel(const float* __restrict__ x, float* __restrict__ xt) {
    int bidx = blockIdx.x;
    int h = bidx & 31;
    int c = (bidx >> 5) % 3;
    int b = bidx / 96;
    __shared__ float s[32][65];
    const float* src = x + (size_t)(((b * 3 + c) * 32 + h) * 32) * 64;
    for (int i = threadIdx.x; i < 2048; i += blockDim.x) {
        int w = i >> 6, t = i & 63;
        s[w][t] = src[i];
    }
    __syncthreads();
    for (int i = threadIdx.x; i < 2048; i += blockDim.x) {
        int t = i >> 5, w = i & 31;
        xt[((size_t)((b * 64 + t) * 3 + c) << 10) + (h << 5) + w] = s[w][t];
    }
}

// -------------------- standard conv3x3 (+optional 2x2 maxpool of input, +ReLU)
template<int CA, int COUT, int COUT_T, int HS, int NBT, int NPIX, bool POOL>
__global__ void __launch_bounds__(256, 2)
conv_std_k(const float* __restrict__ inA, const float* __restrict__ wgt,
           const float* __restrict__ bias, float* __restrict__ out)
{
    constexpr int GP   = COUT / COUT_T;
    constexpr int PXT  = HS * HS / NPIX;
    constexpr int HP   = HS + 1;
    constexpr int CSZ  = HS * HP;
    constexpr int ASZP = CA * CSZ;
    constexpr int WSZ  = COUT * CA * 9;
    extern __shared__ float sm[];
    float* sW  = sm;
    float* sBi = sW + WSZ;
    float* sIn = sBi + COUT;

    const int tid = threadIdx.x, NT = blockDim.x;
    const int bt0 = blockIdx.x * NBT;

    for (int i = tid; i < WSZ; i += NT) {
        int co = i % COUT;
        int rest = i / COUT;
        int ci = rest / 9, kk = rest % 9;
        sW[i] = wgt[(co * CA + ci) * 9 + kk];
    }
    for (int i = tid; i < COUT; i += NT) sBi[i] = bias[i];

    if (POOL) {
        for (int i = tid; i < NBT * CA * HS * HS / 2; i += NT) {
            int e2 = i * 2;
            int nn = e2 / (CA * HS * HS), rr = e2 % (CA * HS * HS);
            int c = rr / (HS * HS), pp = rr % (HS * HS);
            int hh = pp / HS, ww = pp % HS;
            const float* s = inA + (size_t)((bt0 + nn) * CA + c) * (4 * HS * HS)
                                 + (2 * hh) * (2 * HS) + 2 * ww;
            float4 r0 = *reinterpret_cast<const float4*>(s);
            float4 r1 = *reinterpret_cast<const float4*>(s + 2 * HS);
            float* d = sIn + nn * ASZP + c * CSZ + hh * HP + ww;
            d[0] = fmaxf(fmaxf(r0.x, r0.y), fmaxf(r1.x, r1.y));
            d[1] = fmaxf(fmaxf(r0.z, r0.w), fmaxf(r1.z, r1.w));
        }
    } else {
        for (int i = tid; i < NBT * CA * HS * HS / 4; i += NT) {
            int e4 = i * 4;
            int nn = e4 / (CA * HS * HS), rr = e4 % (CA * HS * HS);
            int c = rr / (HS * HS), pp = rr % (HS * HS);
            int hh = pp / HS, ww = pp % HS;
            float4 v = *reinterpret_cast<const float4*>(
                inA + (size_t)(bt0 + nn) * (CA * HS * HS) + rr);
            float* d = sIn + nn * ASZP + c * CSZ + hh * HP + ww;
            d[0] = v.x; d[1] = v.y; d[2] = v.z; d[3] = v.w;
        }
    }
    __syncthreads();

    const int n   = tid / (GP * PXT);
    const int r   = tid % (GP * PXT);
    const int cog = r / PXT;
    const int p   = r % PXT;
    const int h   = p / (HS / NPIX);
    const int w0  = (p % (HS / NPIX)) * NPIX;
    const float* sI = sIn + n * ASZP;

    float acc[COUT_T][NPIX];
    #pragma unroll
    for (int co = 0; co < COUT_T; co++) {
        float b = sBi[cog * COUT_T + co];
        #pragma unroll
        for (int j = 0; j < NPIX; j++) acc[co][j] = b;
    }

    #pragma unroll 1
    for (int ci = 0; ci < CA; ci++) {
        const float* ch = sI + ci * CSZ;
        #pragma unroll
        for (int kh = 0; kh < 3; kh++) {
            int ih = h + kh - 1;
            bool rowok = (ih >= 0) && (ih < HS);
            float v[NPIX + 2];
            #pragma unroll
            for (int j = 0; j < NPIX + 2; j++) {
                int iw = w0 + j - 1;
                v[j] = (rowok && iw >= 0 && iw < HS) ? ch[ih * HP + iw] : 0.f;
            }
            const float* wr = sW + (ci * 9 + kh * 3) * COUT + cog * COUT_T;
            #pragma unroll
            for (int co = 0; co < COUT_T; co++) {
                float wa = wr[co], wb = wr[COUT + co], wc = wr[2 * COUT + co];
                #pragma unroll
                for (int j = 0; j < NPIX; j++)
                    acc[co][j] = fmaf(wa, v[j], fmaf(wb, v[j + 1], fmaf(wc, v[j + 2], acc[co][j])));
            }
        }
    }

    const int btn = bt0 + n;
    #pragma unroll
    for (int co = 0; co < COUT_T; co++) {
        float* op = out + (size_t)((btn * COUT + cog * COUT_T + co) * HS + h) * HS + w0;
        #pragma unroll
        for (int j = 0; j < NPIX; j += 4)
            *reinterpret_cast<float4*>(op + j) =
                make_float4(fmaxf(acc[co][j], 0.f), fmaxf(acc[co][j + 1], 0.f),
                            fmaxf(acc[co][j + 2], 0.f), fmaxf(acc[co][j + 3], 0.f));
    }
}

// -------------------- decoder conv3x3 over [up2x(A), B] (+opt fused mask) ----
template<int CA, int CB, int COUT, int COUT_T, int HS, int NBT, int NPIX, bool FUSE>
__global__ void __launch_bounds__(256, 2)
conv_up_k(const float* __restrict__ inA, const float* __restrict__ inB,
          const float* __restrict__ wgt, const float* __restrict__ bias,
          const float* __restrict__ xtp, const float* __restrict__ owp,
          const float* __restrict__ obp, float* __restrict__ out)
{
    constexpr int CIN  = CA + CB;
    constexpr int HA   = HS / 2;
    constexpr int HAP  = HA + 1;
    constexpr int HP   = HS + 1;
    constexpr int CASZ = HA * HAP;
    constexpr int CBSZ = HS * HP;
    constexpr int ASZP = CA * CASZ;
    constexpr int TSZ  = ASZP + CB * CBSZ;
    constexpr int GP   = COUT / COUT_T;
    constexpr int PXT  = HS * HS / NPIX;
    constexpr int WSZ  = COUT * CIN * 9;
    constexpr int NC   = NPIX / 2 + 2;

    extern __shared__ float sm[];
    float* sW  = sm;
    float* sBi = sW + WSZ;
    float* sOW = sBi + COUT;
    float* sIn = sOW + 18;

    const int tid = threadIdx.x, NT = blockDim.x;
    const int bt0 = blockIdx.x * NBT;

    for (int i = tid; i < WSZ; i += NT) {
        int co = i % COUT;
        int rest = i / COUT;
        int ci = rest / 9, kk = rest % 9;
        sW[i] = wgt[(co * CIN + ci) * 9 + kk];
    }
    for (int i = tid; i < COUT; i += NT) sBi[i] = bias[i];
    if (FUSE) {
        for (int i = tid; i < 18; i += NT) sOW[i] = (i < 16) ? owp[i] : obp[i - 16];
    }
    for (int i = tid; i < NBT * CA * HA * HA / 4; i += NT) {
        int e4 = i * 4;
        int nn = e4 / (CA * HA * HA), rr = e4 % (CA * HA * HA);
        int c = rr / (HA * HA), pp = rr % (HA * HA);
        float4 v = *reinterpret_cast<const float4*>(
            inA + (size_t)(bt0 + nn) * (CA * HA * HA) + rr);
        float* d = sIn + nn * TSZ + c * CASZ + (pp / HA) * HAP + (pp % HA);
        d[0] = v.x; d[1] = v.y; d[2] = v.z; d[3] = v.w;
    }
    for (int i = tid; i < NBT * CB * HS * HS / 4; i += NT) {
        int e4 = i * 4;
        int nn = e4 / (CB * HS * HS), rr = e4 % (CB * HS * HS);
        int c = rr / (HS * HS), pp = rr % (HS * HS);
        float4 v = *reinterpret_cast<const float4*>(
            inB + (size_t)(bt0 + nn) * (CB * HS * HS) + rr);
        float* d = sIn + nn * TSZ + ASZP + c * CBSZ + (pp / HS) * HP + (pp % HS);
        d[0] = v.x; d[1] = v.y; d[2] = v.z; d[3] = v.w;
    }
    __syncthreads();

    const int n   = tid / (GP * PXT);
    const int r   = tid % (GP * PXT);
    const int cog = r / PXT;
    const int p   = r % PXT;
    const int h   = p / (HS / NPIX);
    const int w0  = (p % (HS / NPIX)) * NPIX;
    const float* sI = sIn + n * TSZ;

    float acc[COUT_T][NPIX];
    #pragma unroll
    for (int co = 0; co < COUT_T; co++) {
        float b = sBi[cog * COUT_T + co];
        #pragma unroll
        for (int j = 0; j < NPIX; j++) acc[co][j] = b;
    }

    const int  a    = h >> 1;
    const bool hodd = (h & 1) != 0;
    const int  rowA = hodd ? a : a - 1;
    const int  rowB = hodd ? a + 1 : a;
    const int  cs0  = (w0 >> 1) - 1;

    #pragma unroll 1
    for (int ci = 0; ci < CA; ci++) {
        const float* ch = sI + ci * CASZ;
        float cAr[NC], cBr[NC];
        #pragma unroll
        for (int k = 0; k < NC; k++) {
            int cc = cs0 + k;
            bool cok = (cc >= 0) && (cc < HA);
            cAr[k] = (cok && rowA >= 0) ? ch[rowA * HAP + cc] : 0.f;
            cBr[k] = (cok && rowB < HA) ? ch[rowB * HAP + cc] : 0.f;
        }
        const float* wr = sW + ci * 9 * COUT + cog * COUT_T;
        #pragma unroll
        for (int co = 0; co < COUT_T; co++) {
            float w00 = wr[0 * COUT + co], w01 = wr[1 * COUT + co], w02 = wr[2 * COUT + co];
            float w10 = wr[3 * COUT + co], w11 = wr[4 * COUT + co], w12 = wr[5 * COUT + co];
            float w20 = wr[6 * COUT + co], w21 = wr[7 * COUT + co], w22 = wr[8 * COUT + co];
            float rA0 = hodd ? (w00 + w10) : w00;
            float rA1 = hodd ? (w01 + w11) : w01;
            float rA2 = hodd ? (w02 + w12) : w02;
            float rB0 = hodd ? w20 : (w10 + w20);
            float rB1 = hodd ? w21 : (w11 + w21);
            float rB2 = hodd ? w22 : (w12 + w22);
            float sA0 = rA0, sA01 = rA0 + rA1, sA12 = rA1 + rA2, sA2 = rA2;
            float sB0 = rB0, sB01 = rB0 + rB1, sB12 = rB1 + rB2, sB2 = rB2;
            #pragma unroll
            for (int j = 0; j < NPIX; j++) {
                int lb = (j >> 1) + 1;
                if ((j & 1) == 0) {
                    acc[co][j] = fmaf(cAr[lb - 1], sA0,  acc[co][j]);
                    acc[co][j] = fmaf(cAr[lb],     sA12, acc[co][j]);
                    acc[co][j] = fmaf(cBr[lb - 1], sB0,  acc[co][j]);
                    acc[co][j] = fmaf(cBr[lb],     sB12, acc[co][j]);
                } else {
                    acc[co][j] = fmaf(cAr[lb],     sA01, acc[co][j]);
                    acc[co][j] = fmaf(cAr[lb + 1], sA2,  acc[co][j]);
                    acc[co][j] = fmaf(cBr[lb],     sB01, acc[co][j]);
                    acc[co][j] = fmaf(cBr[lb + 1], sB2,  acc[co][j]);
                }
            }
        }
    }

    #pragma unroll 1
    for (int ci = 0; ci < CB; ci++) {
        const float* ch = sI + ASZP + ci * CBSZ;
        #pragma unroll
        for (int kh = 0; kh < 3; kh++) {
            int ih = h + kh - 1;
            bool rowok = (ih >= 0) && (ih < HS);
            float v[NPIX + 2];
            #pragma unroll
            for (int j = 0; j < NPIX + 2; j++) {
                int iw = w0 + j - 1;
                v[j] = (rowok && iw >= 0 && iw < HS) ? ch[ih * HP + iw] : 0.f;
            }
            const float* wr = sW + ((CA + ci) * 9 + kh * 3) * COUT + cog * COUT_T;
            #pragma unroll
            for (int co = 0; co < COUT_T; co++) {
                float wa = wr[co], wb = wr[COUT + co], wc = wr[2 * COUT + co];
                #pragma unroll
                for (int j = 0; j < NPIX; j++)
                    acc[co][j] = fmaf(wa, v[j], fmaf(wb, v[j + 1], fmaf(wc, v[j + 2], acc[co][j])));
            }
        }
    }

    const int btn = bt0 + n;
    if constexpr (FUSE) {
        float m0a[NPIX], m1a[NPIX];
        #pragma unroll
        for (int j = 0; j < NPIX; j++) {
            float l0 = sOW[16], l1 = sOW[17];
            #pragma unroll
            for (int co = 0; co < COUT_T; co++) {
                float dv = fmaxf(acc[co][j], 0.f);
                l0 = fmaf(dv, sOW[co], l0);
                l1 = fmaf(dv, sOW[8 + co], l1);
            }
            float mx = fmaxf(fmaxf(l0, l1), 1.0f);
            float e0 = expf(l0 - mx), e1v = expf(l1 - mx), e2v = expf(1.0f - mx);
            float inv = 1.0f / (e0 + e1v + e2v);
            m0a[j] = e0 * inv;
            m1a[j] = e1v * inv;
        }
        const float* xp = xtp + ((size_t)btn * 3 << 10) + (h << 5) + w0;
        float* fp = out + (size_t)btn * FEAT + (h << 5) + w0;
        #pragma unroll
        for (int c = 0; c < 3; c++) {
            float4 xa = *reinterpret_cast<const float4*>(xp + ((size_t)c << 10));
            float4 xb = *reinterpret_cast<const float4*>(xp + ((size_t)c << 10) + 4);
            float* f0 = fp + ((size_t)c << 10);
            float* f1 = fp + ((size_t)(3 + c) << 10);
            *reinterpret_cast<float4*>(f0) =
                make_float4(m0a[0] * xa.x, m0a[1] * xa.y, m0a[2] * xa.z, m0a[3] * xa.w);
            *reinterpret_cast<float4*>(f0 + 4) =
                make_float4(m0a[4] * xb.x, m0a[5] * xb.y, m0a[6] * xb.z, m0a[7] * xb.w);
            *reinterpret_cast<float4*>(f1) =
                make_float4(m1a[0] * xa.x, m1a[1] * xa.y, m1a[2] * xa.z, m1a[3] * xa.w);
            *reinterpret_cast<float4*>(f1 + 4) =
                make_float4(m1a[4] * xb.x, m1a[5] * xb.y, m1a[6] * xb.z, m1a[7] * xb.w);
        }
    } else {
        #pragma unroll
        for (int co = 0; co < COUT_T; co++) {
            float* op = out + (size_t)((btn * COUT + cog * COUT_T + co) * HS + h) * HS + w0;
            #pragma unroll
            for (int j = 0; j < NPIX; j += 4)
                *reinterpret_cast<float4*>(op + j) =
                    make_float4(fmaxf(acc[co][j], 0.f), fmaxf(acc[co][j + 1], 0.f),
                                fmaxf(acc[co][j + 2], 0.f), fmaxf(acc[co][j + 3], 0.f));
        }
    }
}

// -------------------- GEMM1: split-K, tf32 mma.sync (m16n8k8), BK16 ----------
__device__ __forceinline__ unsigned f2tf(float f) {
    unsigned r;
    asm("cvt.rna.tf32.f32 %0, %1;" : "=r"(r) : "f"(f));
    return r;
}

__global__ void __launch_bounds__(256)
sgemm1_k(const float* __restrict__ A, const float* __restrict__ Bm,
         float* __restrict__ Cpart)
{
    constexpr int M = BT, N = HID, K = FEAT;
    constexpr int BM = 128, BN = 64, BK = 16;
    constexpr int KS = K / SPLITS;                 // 768
    constexpr int SAP = BM + 8;                    // 136
    constexpr int SBP = BN + 8;                    // 72

    __shared__ float sA[BK][SAP];
    __shared__ float sB[BK][SBP];

    const int tid  = threadIdx.x;
    const int warp = tid >> 5;
    const int lane = tid & 31;
    const int gid  = lane >> 2;
    const int tig  = lane & 3;
    const int wm   = warp & 3;
    const int wn   = warp >> 2;
    const int m_w  = wm * 32;
    const int n_w  = wn * 32;

    const int bm = blockIdx.y * BM;
    const int bn = blockIdx.x * BN;
    const int kbase = blockIdx.z * KS;

    const int c4 = tid & 3;
    const int r0 = tid >> 2;

    float c[2][4][4];
    #pragma unroll
    for (int mi = 0; mi < 2; mi++)
        #pragma unroll
        for (int ni = 0; ni < 4; ni++)
            #pragma unroll
            for (int f = 0; f < 4; f++) c[mi][ni][f] = 0.f;

    for (int k0 = kbase; k0 < kbase + KS; k0 += BK) {
        #pragma unroll
        for (int q = 0; q < 2; q++) {
            int rr = r0 + 64 * q;
            float4 av = *reinterpret_cast<const float4*>(&A[(size_t)(bm + rr) * K + k0 + c4 * 4]);
            sA[c4 * 4 + 0][rr] = __uint_as_float(f2tf(av.x));
            sA[c4 * 4 + 1][rr] = __uint_as_float(f2tf(av.y));
            sA[c4 * 4 + 2][rr] = __uint_as_float(f2tf(av.z));
            sA[c4 * 4 + 3][rr] = __uint_as_float(f2tf(av.w));
        }
        {
            int kk = tid >> 4;
            int cc = (tid & 15) * 4;
            int gcol = bn + cc;
            float b0 = (gcol + 0 < N) ? Bm[(size_t)(k0 + kk) * N + gcol + 0] : 0.f;
            float b1 = (gcol + 1 < N) ? Bm[(size_t)(k0 + kk) * N + gcol + 1] : 0.f;
            float b2 = (gcol + 2 < N) ? Bm[(size_t)(k0 + kk) * N + gcol + 2] : 0.f;
            float b3 = (gcol + 3 < N) ? Bm[(size_t)(k0 + kk) * N + gcol + 3] : 0.f;
            sB[kk][cc + 0] = __uint_as_float(f2tf(b0));
            sB[kk][cc + 1] = __uint_as_float(f2tf(b1));
            sB[kk][cc + 2] = __uint_as_float(f2tf(b2));
            sB[kk][cc + 3] = __uint_as_float(f2tf(b3));
        }
        __syncthreads();

        #pragma unroll
        for (int kc = 0; kc < BK; kc += 8) {
            unsigned bf[4][2];
            #pragma unroll
            for (int ni = 0; ni < 4; ni++) {
                bf[ni][0] = __float_as_uint(sB[kc + tig][n_w + ni * 8 + gid]);
                bf[ni][1] = __float_as_uint(sB[kc + tig + 4][n_w + ni * 8 + gid]);
            }
            #pragma unroll
            for (int mi = 0; mi < 2; mi++) {
                int mrow = m_w + mi * 16 + gid;
                unsigned a0 = __float_as_uint(sA[kc + tig][mrow]);
                unsigned a1 = __float_as_uint(sA[kc + tig][mrow + 8]);
                unsigned a2 = __float_as_uint(sA[kc + tig + 4][mrow]);
                unsigned a3 = __float_as_uint(sA[kc + tig + 4][mrow + 8]);
                #pragma unroll
                for (int ni = 0; ni < 4; ni++) {
                    asm volatile(
                        "mma.sync.aligned.m16n8k8.row.col.f32.tf32.tf32.f32 "
                        "{%0,%1,%2,%3}, {%4,%5,%6,%7}, {%8,%9}, {%0,%1,%2,%3};"
                        : "+f"(c[mi][ni][0]), "+f"(c[mi][ni][1]),
                          "+f"(c[mi][ni][2]), "+f"(c[mi][ni][3])
                        : "r"(a0), "r"(a1), "r"(a2), "r"(a3),
                          "r"(bf[ni][0]), "r"(bf[ni][1]));
                }
            }
        }
        __syncthreads();
    }

    float* Cp = Cpart + (size_t)blockIdx.z * M * N;
    #pragma unroll
    for (int mi = 0; mi < 2; mi++) {
        int row0 = bm + m_w + mi * 16 + gid;
        #pragma unroll
        for (int ni = 0; ni < 4; ni++) {
            int col0 = bn + n_w + ni * 8 + 2 * tig;
            if (col0 < N) {
                Cp[(size_t)row0 * N + col0]       = c[mi][ni][0];
                Cp[(size_t)(row0 + 8) * N + col0] = c[mi][ni][2];
            }
            if (col0 + 1 < N) {
                Cp[(size_t)row0 * N + col0 + 1]       = c[mi][ni][1];
                Cp[(size_t)(row0 + 8) * N + col0 + 1] = c[mi][ni][3];
            }
        }
    }
}

// -------------------- GEMM2 with fused split-K reduce of h1 ------------------
__global__ void __launch_bounds__(256)
sgemm2_k(const float* __restrict__ part, const float* __restrict__ ab,
         const float* __restrict__ Bm, const float* __restrict__ bias,
         float* __restrict__ C)
{
    constexpr int M = BT, N = HID, K = HID;
    constexpr int BM = 64, BN = 64, BK = 16;
    __shared__ float sA[BK][BM + 1];
    __shared__ float sB[BK][BN];
    const int tid = threadIdx.x;
    const int tx = tid % 16;
    const int ty = tid / 16;
    const int bm = blockIdx.y * BM;
    const int bn = blockIdx.x * BN;

    float acc[4][4];
    #pragma unroll
    for (int i = 0; i < 4; i++)
        #pragma unroll
        for (int j = 0; j < 4; j++) acc[i][j] = 0.f;

    for (int k0 = 0; k0 < K; k0 += BK) {
        for (int i = tid; i < BM * BK; i += 256) {
            int m = i / BK, kk = i % BK;
            float v = 0.f;
            if (k0 + kk < K) {
                size_t off = (size_t)(bm + m) * K + k0 + kk;
                float t = ab[k0 + kk];
                #pragma unroll
                for (int s = 0; s < SPLITS; s++) t += part[(size_t)s * M * K + off];
                v = fmaxf(t, 0.f);
            }
            sA[kk][m] = v;
        }
        for (int i = tid; i < BK * BN; i += 256) {
            int kk = i / BN, n = i % BN;
            sB[kk][n] = (k0 + kk < K && bn + n < N) ? Bm[(size_t)(k0 + kk) * N + bn + n] : 0.f;
        }
        __syncthreads();
        #pragma unroll
        for (int kk = 0; kk < BK; kk++) {
            float a[4], b[4];
            #pragma unroll
            for (int i = 0; i < 4; i++) a[i] = sA[kk][ty * 4 + i];
            #pragma unroll
            for (int j = 0; j < 4; j++) b[j] = sB[kk][tx * 4 + j];
            #pragma unroll
            for (int i = 0; i < 4; i++)
                #pragma unroll
                for (int j = 0; j < 4; j++) acc[i][j] = fmaf(a[i], b[j], acc[i][j]);
        }
        __syncthreads();
    }

    #pragma unroll
    for (int i = 0; i < 4; i++) {
        int m = bm + ty * 4 + i;
        #pragma unroll
        for (int j = 0; j < 4; j++) {
            int n = bn + tx * 4 + j;
            if (n >= N) continue;
            C[(size_t)m * N + n] = fmaxf(acc[i][j] + bias[n], 0.f);
        }
    }
}

// -------------------- final 200->4 + tanh scale ------------------------------
__global__ void loc3_kernel(const float* __restrict__ h2, const float* __restrict__ w3,
                            const float* __restrict__ b3, float* __restrict__ out)
{
    int idx = blockIdx.x * blockDim.x + threadIdx.x;
    if (idx >= BT * 4) return;
    int m = idx >> 2, j = idx & 3;
    float acc = b3[j];
    const float* hp = h2 + (size_t)m * HID;
    #pragma unroll 8
    for (int k = 0; k < HID; k++) acc = fmaf(hp[k], w3[k * 4 + j], acc);
    out[idx] = tanhf(acc) * 16.f + 16.f;
}

// -------------------- launch --------------------------------------------------
extern "C" void kernel_launch(void* const* d_in, const int* in_sizes, int n_in,
                              void* d_out, int out_size)
{
    const float* x   = (const float*)d_in[0];
    const float* ew1 = (const float*)d_in[1];
    const float* eb1 = (const float*)d_in[2];
    const float* ew2 = (const float*)d_in[3];
    const float* eb2 = (const float*)d_in[4];
    const float* ew3 = (const float*)d_in[5];
    const float* eb3 = (const float*)d_in[6];
    const float* dw2 = (const float*)d_in[7];
    const float* db2 = (const float*)d_in[8];
    const float* dw1 = (const float*)d_in[9];
    const float* db1 = (const float*)d_in[10];
    const float* ow  = (const float*)d_in[11];
    const float* ob  = (const float*)d_in[12];
    const float* lw1 = (const float*)d_in[13];
    const float* lb1 = (const float*)d_in[14];
    const float* lw2 = (const float*)d_in[15];
    const float* lb2 = (const float*)d_in[16];
    const float* lw3 = (const float*)d_in[17];
    const float* lb3 = (const float*)d_in[18];
    float* out = (float*)d_out;

    float *xt, *e1, *e2, *e3, *d2v, *feat, *h2, *part;
    cudaGetSymbolAddress((void**)&xt,   g_xt);
    cudaGetSymbolAddress((void**)&e1,   g_e1);
    cudaGetSymbolAddress((void**)&e2,   g_e2);
    cudaGetSymbolAddress((void**)&e3,   g_e3);
    cudaGetSymbolAddress((void**)&d2v,  g_d2);
    cudaGetSymbolAddress((void**)&feat, g_feat);
    cudaGetSymbolAddress((void**)&h2,   g_h2);
    cudaGetSymbolAddress((void**)&part, g_part);

    constexpr int SM_E1 = (3 * 8 * 9  + 8  + 2 * 3 * 32 * 33) * 4;
    constexpr int SM_E2 = (8 * 16 * 9 + 16 + 4 * 8 * 16 * 17) * 4;
    constexpr int SM_E3 = (16 * 32 * 9 + 32 + 8 * 16 * 8 * 9) * 4;
    constexpr int SM_D2 = (48 * 16 * 9 + 16 + 18 + 2 * (32 * 8 * 9 + 16 * 16 * 17)) * 4;
    constexpr int SM_D1 = (24 * 8 * 9 + 8 + 18 + 2 * (16 * 16 * 17 + 8 * 32 * 33)) * 4;

    cudaFuncSetAttribute((const void*)conv_std_k<8, 16, 8, 16, 4, 8, true>,
                         cudaFuncAttributeMaxDynamicSharedMemorySize, SM_E2);
    cudaFuncSetAttribute((const void*)conv_std_k<16, 32, 8, 8, 8, 8, true>,
                         cudaFuncAttributeMaxDynamicSharedMemorySize, SM_E3);
    cudaFuncSetAttribute((const void*)conv_up_k<32, 16, 16, 4, 16, 2, 8, false>,
                         cudaFuncAttributeMaxDynamicSharedMemorySize, SM_D2);
    cudaFuncSetAttribute((const void*)conv_up_k<16, 8, 8, 8, 32, 2, 8, true>,
                         cudaFuncAttributeMaxDynamicSharedMemorySize, SM_D1);

    // 1) permute
    permute_kernel<<<32 * 3 * 32, 256>>>(x, xt);
    // 2) e1 = relu(conv 3->8 @32)
    conv_std_k<3, 8, 8, 32, 2, 8, false><<<BT / 2, 256, SM_E1>>>(xt, ew1, eb1, e1);
    // 3) e2 = relu(conv pool(e1) 8->16 @16)
    conv_std_k<8, 16, 8, 16, 4, 8, true><<<BT / 4, 256, SM_E2>>>(e1, ew2, eb2, e2);
    // 4) e3 = relu(conv pool(e2) 16->32 @8)
    conv_std_k<16, 32, 8, 8, 8, 8, true><<<BT / 8, 256, SM_E3>>>(e2, ew3, eb3, e3);
    // 5) d2 = relu(conv [up(e3), e2] 48->16 @16)
    conv_up_k<32, 16, 16, 4, 16, 2, 8, false><<<BT / 2, 256, SM_D2>>>(
        e3, e2, dw2, db2, nullptr, nullptr, nullptr, d2v);
    // 6) d1 conv + 1x1 + softmax + masked features, fused -> feat
    conv_up_k<16, 8, 8, 8, 32, 2, 8, true><<<BT / 2, 256, SM_D1>>>(
        d2v, e1, dw1, db1, xt, ow, ob, feat);
    // 7) h1-partials = feat @ lw1 via split-K x8, tf32 mma.sync
    sgemm1_k<<<dim3(4, BT / 128, SPLITS), 256>>>(feat, lw1, part);
    // 8) h2 = relu(relu(lb1 + sum parts) @ lw2 + lb2)
    sgemm2_k<<<dim3(4, BT / 64), 256>>>(part, lb1, lw2, lb2, h2);
    // 9) out = tanh(h2 @ lw3 + lb3)*16+16
    loc3_kernel<<<(BT * 4 + 255) / 256, 256>>>(h2, lw3, lb3, out);
}